// round 6
// baseline (speedup 1.0000x reference)
#include <cuda_runtime.h>
#include <cuda_bf16.h>
#include <math.h>
#include <stdint.h>

#define B_  16
#define L_  1024
#define C_  128
#define H_  512
#define LC_ (L_*C_)      // 131072
#define M_  (B_*L_)      // 16384

// ---------------- device scratch ----------------
__device__ float g_h  [M_*H_];        // 32 MB hidden activations (fp32)
__device__ float g_eps[M_*C_];
__device__ float g_za [M_*C_];
__device__ float g_zb [M_*C_];
__device__ float g_ent[LC_];
__device__ float g_p1[(L_/2)*(C_/2)];
__device__ float g_p2[(L_/4)*(C_/4)];
__device__ float g_p3[(L_/8)*(C_/8)];
__device__ float g_part[1024];
__device__ float g_T[4];
__device__ float g_stats[2];
// activation splits (bf16 x3)
__device__ __nv_bfloat16 g_za0[M_*C_], g_za1[M_*C_], g_za2[M_*C_];   // z  [16384,128]
__device__ __nv_bfloat16 g_h0 [M_*H_], g_h1 [M_*H_], g_h2 [M_*H_];   // h  [16384,512]
// weight splits, transposed [N,K] row-major (K contiguous)
__device__ __nv_bfloat16 g_b1t0[H_*C_], g_b1t1[H_*C_], g_b1t2[H_*C_]; // [512,128]
__device__ __nv_bfloat16 g_b2t0[C_*H_], g_b2t1[C_*H_], g_b2t2[C_*H_]; // [128,512]

// ---------------- helpers ----------------
__device__ __forceinline__ uint32_t smem_u32(const void* p) {
    uint32_t a;
    asm("{ .reg .u64 t; cvta.to.shared.u64 t, %1; cvt.u32.u64 %0, t; }" : "=r"(a) : "l"(p));
    return a;
}
__device__ __forceinline__ void cp_async16(uint32_t s, const void* g) {
    asm volatile("cp.async.cg.shared.global [%0], [%1], 16;" :: "r"(s), "l"(g) : "memory");
}
__device__ __forceinline__ void ldsm_x4(uint32_t* r, uint32_t addr) {
    asm volatile("ldmatrix.sync.aligned.m8n8.x4.shared.b16 {%0,%1,%2,%3}, [%4];"
                 : "=r"(r[0]), "=r"(r[1]), "=r"(r[2]), "=r"(r[3]) : "r"(addr));
}
__device__ __forceinline__ void mma16816(float* d, const uint32_t* a, const uint32_t* b) {
    asm volatile(
        "mma.sync.aligned.m16n8k16.row.col.f32.bf16.bf16.f32 "
        "{%0,%1,%2,%3}, {%4,%5,%6,%7}, {%8,%9}, {%0,%1,%2,%3};"
        : "+f"(d[0]), "+f"(d[1]), "+f"(d[2]), "+f"(d[3])
        : "r"(a[0]), "r"(a[1]), "r"(a[2]), "r"(a[3]), "r"(b[0]), "r"(b[1]));
}
__device__ __forceinline__ float gelu_f(float x) {
    float x3 = x * x * x;
    float u  = 0.7978845608028654f * (x + 0.044715f * x3);
    return 0.5f * x * (1.0f + tanhf(u));
}
__device__ __forceinline__ void split3(float x, unsigned short& h0, unsigned short& h1, unsigned short& h2) {
    __nv_bfloat16 b0 = __float2bfloat16_rn(x);
    float r1 = x - __bfloat162float(b0);
    __nv_bfloat16 b1 = __float2bfloat16_rn(r1);
    float r2 = r1 - __bfloat162float(b1);
    __nv_bfloat16 b2 = __float2bfloat16_rn(r2);
    h0 = __bfloat16_as_ushort(b0);
    h1 = __bfloat16_as_ushort(b1);
    h2 = __bfloat16_as_ushort(b2);
}

// ---------------- weight prep: transpose + 3-way split ------------------
__global__ __launch_bounds__(256) void prep_k(const float* __restrict__ W1, const float* __restrict__ W2)
{
    int t = blockIdx.x * 256 + threadIdx.x;   // 131072 total
    float x; int idx;
    __nv_bfloat16 *d0, *d1, *d2;
    if (t < H_ * C_) {                        // B1t [512,128] from W1[128,512]
        idx = t; int n = idx >> 7, k = idx & 127;
        x = W1[k * H_ + n];
        d0 = g_b1t0; d1 = g_b1t1; d2 = g_b1t2;
    } else {                                  // B2t [128,512] from W2[512,128]
        idx = t - H_ * C_; int n = idx >> 9, k = idx & 511;
        x = W2[k * C_ + n];
        d0 = g_b2t0; d1 = g_b2t1; d2 = g_b2t2;
    }
    unsigned short h0, h1, h2;
    split3(x, h0, h1, h2);
    d0[idx] = __ushort_as_bfloat16(h0);
    d1[idx] = __ushort_as_bfloat16(h1);
    d2[idx] = __ushort_as_bfloat16(h2);
}

// ---------------- streaming splitters (fp32 -> 3x bf16) ------------------
__global__ __launch_bounds__(256) void splitz_k(const float* __restrict__ src)
{
    int i = blockIdx.x * 256 + threadIdx.x;   // < M_*C_/4
    float4 v = *(const float4*)(src + (size_t)i * 4);
    float x[4] = { v.x, v.y, v.z, v.w };
    unsigned short s0[4], s1[4], s2[4];
#pragma unroll
    for (int j = 0; j < 4; j++) split3(x[j], s0[j], s1[j], s2[j]);
    ((uint2*)g_za0)[i] = make_uint2((uint32_t)s0[0] | ((uint32_t)s0[1] << 16), (uint32_t)s0[2] | ((uint32_t)s0[3] << 16));
    ((uint2*)g_za1)[i] = make_uint2((uint32_t)s1[0] | ((uint32_t)s1[1] << 16), (uint32_t)s1[2] | ((uint32_t)s1[3] << 16));
    ((uint2*)g_za2)[i] = make_uint2((uint32_t)s2[0] | ((uint32_t)s2[1] << 16), (uint32_t)s2[2] | ((uint32_t)s2[3] << 16));
}
__global__ __launch_bounds__(256) void splith_k()
{
    int i = blockIdx.x * 256 + threadIdx.x;   // < M_*H_/4
    float4 v = *(const float4*)(g_h + (size_t)i * 4);
    float x[4] = { v.x, v.y, v.z, v.w };
    unsigned short s0[4], s1[4], s2[4];
#pragma unroll
    for (int j = 0; j < 4; j++) split3(x[j], s0[j], s1[j], s2[j]);
    ((uint2*)g_h0)[i] = make_uint2((uint32_t)s0[0] | ((uint32_t)s0[1] << 16), (uint32_t)s0[2] | ((uint32_t)s0[3] << 16));
    ((uint2*)g_h1)[i] = make_uint2((uint32_t)s1[0] | ((uint32_t)s1[1] << 16), (uint32_t)s1[2] | ((uint32_t)s1[3] << 16));
    ((uint2*)g_h2)[i] = make_uint2((uint32_t)s2[0] | ((uint32_t)s2[1] << 16), (uint32_t)s2[2] | ((uint32_t)s2[3] << 16));
}

// ---------------- split-fp32 GEMM via bf16 mma.sync ---------------------
// EXACT R4-measured-fast configuration: 256 threads, 8 warps (64x32 warp
// tiles), CTA 128x128, BK=32, double-buffered cp.async, pre-split bf16 A & B.
static constexpr int TERMB = 10240;   // 128 rows x 80B (64B data + 16B pad)
static constexpr int BOFF  = 3 * TERMB;
static constexpr int BUFB  = 6 * TERMB;   // 61440
static constexpr int SMEMB = 2 * BUFB;    // 122880

template<int KTOT, bool GELU>
__global__ __launch_bounds__(256, 1)
void gemm_mma(const __nv_bfloat16* __restrict__ A0, const __nv_bfloat16* __restrict__ A1,
              const __nv_bfloat16* __restrict__ A2,
              const __nv_bfloat16* __restrict__ Bt0, const __nv_bfloat16* __restrict__ Bt1,
              const __nv_bfloat16* __restrict__ Bt2,
              const float* __restrict__ bias, const float* __restrict__ tw, float t_feat,
              float* __restrict__ out, int Ntot)
{
    extern __shared__ char smem[];
    const uint32_t sb = smem_u32(smem);
    const int tid = threadIdx.x, lane = tid & 31, wid = tid >> 5;
    const int m0 = blockIdx.y * 128, n0 = blockIdx.x * 128;
    const int wm = (wid >> 2) * 64, wn = (wid & 3) * 32;

    const __nv_bfloat16* At[3] = { A0, A1, A2 };
    const __nv_bfloat16* Bt[3] = { Bt0, Bt1, Bt2 };

    float acc[4][4][4];
#pragma unroll
    for (int a = 0; a < 4; a++)
#pragma unroll
        for (int b = 0; b < 4; b++)
#pragma unroll
            for (int c = 0; c < 4; c++) acc[a][b][c] = 0.0f;

    auto load_tile = [&](int kt, int buf) {
        uint32_t base = sb + buf * BUFB;
#pragma unroll
        for (int i = 0; i < 6; i++) {
            int t = tid + i * 256;
            int term = t >> 9, rem = t & 511;
            int row = rem >> 2, ch = rem & 3;
            cp_async16(base + term * TERMB + row * 80 + ch * 16,
                       At[term] + (size_t)(m0 + row) * KTOT + kt * 32 + ch * 8);
        }
#pragma unroll
        for (int i = 0; i < 6; i++) {
            int t = tid + i * 256;
            int term = t >> 9, rem = t & 511;
            int row = rem >> 2, ch = rem & 3;
            cp_async16(base + BOFF + term * TERMB + row * 80 + ch * 16,
                       Bt[term] + (size_t)(n0 + row) * KTOT + kt * 32 + ch * 8);
        }
        asm volatile("cp.async.commit_group;" ::: "memory");
    };

    constexpr int NKT = KTOT / 32;
    load_tile(0, 0);
    int buf = 0;

    const int PA[6] = { 0, 0, 1, 1, 0, 2 };
    const int PB[6] = { 0, 1, 0, 1, 2, 0 };

#pragma unroll 1
    for (int kt = 0; kt < NKT; kt++) {
        if (kt + 1 < NKT) {
            load_tile(kt + 1, buf ^ 1);
            asm volatile("cp.async.wait_group 1;" ::: "memory");
        } else {
            asm volatile("cp.async.wait_group 0;" ::: "memory");
        }
        __syncthreads();

        uint32_t base = sb + buf * BUFB;
#pragma unroll
        for (int kk = 0; kk < 2; kk++) {
            uint32_t aF[3][4][4];
            uint32_t bF[3][4][2];
#pragma unroll
            for (int t = 0; t < 3; t++) {
#pragma unroll
                for (int mi = 0; mi < 4; mi++) {
                    uint32_t addr = base + t * TERMB
                        + (wm + mi * 16 + (lane & 15)) * 80
                        + kk * 32 + (lane >> 4) * 16;
                    ldsm_x4(aF[t][mi], addr);
                }
#pragma unroll
                for (int nt = 0; nt < 2; nt++) {
                    int row = wn + nt * 16 + ((lane >> 4) & 1) * 8 + (lane & 7);
                    uint32_t addr = base + BOFF + t * TERMB
                        + row * 80 + kk * 32 + ((lane >> 3) & 1) * 16;
                    uint32_t r[4];
                    ldsm_x4(r, addr);
                    bF[t][nt * 2][0]     = r[0]; bF[t][nt * 2][1]     = r[1];
                    bF[t][nt * 2 + 1][0] = r[2]; bF[t][nt * 2 + 1][1] = r[3];
                }
            }
#pragma unroll
            for (int p = 0; p < 6; p++) {
#pragma unroll
                for (int mi = 0; mi < 4; mi++)
#pragma unroll
                    for (int ni = 0; ni < 4; ni++)
                        mma16816(acc[mi][ni], aF[PA[p]][mi], bF[PB[p]][ni]);
            }
        }
        __syncthreads();
        buf ^= 1;
    }

    // ---- epilogue: bias (+time) (+gelu), fp32 float2 stores ----
#pragma unroll
    for (int mi = 0; mi < 4; mi++) {
#pragma unroll
        for (int ni = 0; ni < 4; ni++) {
            int r0 = m0 + wm + mi * 16 + (lane >> 2);
            int r1 = r0 + 8;
            int c  = n0 + wn + ni * 8 + (lane & 3) * 2;
            float bz0 = __ldg(bias + c);
            float bz1 = __ldg(bias + c + 1);
            if (GELU) { bz0 += t_feat * __ldg(tw + c); bz1 += t_feat * __ldg(tw + c + 1); }
            float v00 = acc[mi][ni][0] + bz0;
            float v01 = acc[mi][ni][1] + bz1;
            float v10 = acc[mi][ni][2] + bz0;
            float v11 = acc[mi][ni][3] + bz1;
            if (GELU) {
                v00 = gelu_f(v00); v01 = gelu_f(v01);
                v10 = gelu_f(v10); v11 = gelu_f(v11);
            }
            *(float2*)(out + (size_t)r0 * Ntot + c) = make_float2(v00, v01);
            *(float2*)(out + (size_t)r1 * Ntot + c) = make_float2(v10, v11);
        }
    }
}

// ---------------- entropy map + obs_err partial stats ----------------
__global__ __launch_bounds__(256)
void stats_k(const float* __restrict__ z, const float* __restrict__ y,
             const float* __restrict__ msk)
{
    int tid = threadIdx.x;
    int i = blockIdx.x * 256 + tid;

    float sa = 0.0f;
#pragma unroll
    for (int b = 0; b < B_; b++) sa += fabsf(g_eps[(size_t)b * LC_ + i]);
    g_ent[i] = sa * (1.0f / B_);

    float s = 0.0f, sq = 0.0f;
#pragma unroll
    for (int b = 0; b < B_; b++) {
        size_t o = (size_t)b * LC_ + i;
        float e = (z[o] - y[o]) * msk[o];
        s += e; sq += e * e;
    }
    __shared__ float rs[256], rq[256];
    rs[tid] = s; rq[tid] = sq;
    __syncthreads();
    for (int st = 128; st > 0; st >>= 1) {
        if (tid < st) { rs[tid] += rs[tid + st]; rq[tid] += rq[tid + st]; }
        __syncthreads();
    }
    if (tid == 0) { g_part[blockIdx.x] = rs[0]; g_part[512 + blockIdx.x] = rq[0]; }
}

// ---------------- hierarchical pooling ----------------
__global__ __launch_bounds__(256)
void pool_k()
{
    int t = blockIdx.x * 256 + threadIdx.x;
    int w, idx; float* dst;
    if      (t < 32768) { w = 2; dst = g_p1; idx = t; }
    else if (t < 40960) { w = 4; dst = g_p2; idx = t - 32768; }
    else if (t < 43008) { w = 8; dst = g_p3; idx = t - 40960; }
    else return;
    int Cs = C_ / w;
    int pr = idx / Cs, pc = idx % Cs;
    float s = 0.0f;
    for (int a = 0; a < w; a++)
        for (int b = 0; b < w; b++)
            s += g_ent[(pr * w + a) * C_ + pc * w + b];
    dst[idx] = s / (float)(w * w);
}

// ---------------- radix select (warp-aggregated) + var finalize ----------
__global__ __launch_bounds__(1024)
void select_k()
{
    int bs = blockIdx.x;
    int tid = threadIdx.x;
    int lane = tid & 31;

    if (bs == 4) {
        __shared__ float rs[1024], rq[1024];
        rs[tid] = (tid < 512) ? g_part[tid] : 0.0f;
        rq[tid] = (tid < 512) ? g_part[512 + tid] : 0.0f;
        __syncthreads();
        for (int st = 512; st > 0; st >>= 1) {
            if (tid < st) { rs[tid] += rs[tid + st]; rq[tid] += rq[tid + st]; }
            __syncthreads();
        }
        if (tid == 0) { g_stats[0] = rs[0]; g_stats[1] = rq[0]; }
        return;
    }

    const float* data; int n, K;
    switch (bs) {
        case 0: data = g_ent; n = 131072; K = 26214; break;
        case 1: data = g_p1;  n = 32768;  K = 6553;  break;
        case 2: data = g_p2;  n = 8192;   K = 1638;  break;
        default:data = g_p3;  n = 2048;   K = 409;   break;
    }

    __shared__ unsigned hist[256];
    __shared__ unsigned s_pref, s_k;
    unsigned pref = 0, kk = (unsigned)K;

    for (int p = 0; p < 4; p++) {
        int shift = 24 - 8 * p;
        unsigned mask_hi = (p == 0) ? 0u : (0xFFFFFFFFu << (32 - 8 * p));
        if (tid < 256) hist[tid] = 0;
        __syncthreads();
        for (int i = tid; i < n; i += 1024) {
            unsigned u = __float_as_uint(data[i]);
            bool ok = ((u & mask_hi) == pref);
            unsigned bin = (u >> shift) & 255;
            unsigned valid = __ballot_sync(0xFFFFFFFFu, ok);
            unsigned same  = __match_any_sync(0xFFFFFFFFu, bin);
            if (ok) {
                unsigned mm = same & valid;
                if ((int)(__ffs(mm) - 1) == lane)
                    atomicAdd(&hist[bin], __popc(mm));
            }
        }
        __syncthreads();
        if (tid == 0) {
            unsigned cum = 0; int sel = 0;
            for (int b = 255; b >= 0; b--) {
                unsigned c = hist[b];
                if (cum + c >= kk) { sel = b; break; }
                cum += c;
            }
            s_pref = pref | ((unsigned)sel << shift);
            s_k = kk - cum;
        }
        __syncthreads();
        pref = s_pref; kk = s_k;
        __syncthreads();
    }
    if (tid == 0) g_T[bs] = __uint_as_float(pref);
}

// ---------------- final update ----------------
__global__ __launch_bounds__(256)
void update_k(const float* __restrict__ z, const float* __restrict__ y,
              const float* __restrict__ msk, float* __restrict__ out,
              float base_a, float base_b, float h_lam)
{
    int i = blockIdx.x * 256 + threadIdx.x;
    int l = i / C_, c = i % C_;

    int sfound = -1; float ent = 0.0f;
    float v0 = g_ent[i];
    if (v0 >= g_T[0]) { sfound = 0; ent = v0; }
    else {
        float v1 = g_p1[(l >> 1) * (C_ / 2) + (c >> 1)];
        if (v1 >= g_T[1]) { sfound = 1; ent = v1; }
        else {
            float v2 = g_p2[(l >> 2) * (C_ / 4) + (c >> 2)];
            if (v2 >= g_T[2]) { sfound = 2; ent = v2; }
            else {
                float v3 = g_p3[(l >> 3) * (C_ / 8) + (c >> 3)];
                if (v3 >= g_T[3]) { sfound = 3; ent = v3; }
            }
        }
    }

    if (sfound < 0) {
#pragma unroll
        for (int b = 0; b < B_; b++) {
            size_t o = (size_t)b * LC_ + i;
            out[o] = z[o];
        }
        return;
    }

    const float invN = 1.0f / (float)(B_ * LC_);
    float mean = g_stats[0] * invN;
    float var  = g_stats[1] * invN - mean * mean;
    float inv_d = 1.0f / (var + 1e-8f);

    float om1 = (ent > 0.1f ? 1.0f : 0.0f) + (ent > 0.5f ? 1.0f : 0.0f);
    float corr = 1.0f + om1 * 0.5f * h_lam
               + om1 * (om1 - 1.0f) * (1.0f / 6.0f) * h_lam * h_lam;
    float gs = 2.0f * ent / (ent + 1.0f);
    float bb = base_b * corr;

#pragma unroll
    for (int b = 0; b < B_; b++) {
        size_t o = (size_t)b * LC_ + i;
        float zv = z[o];
        float gd = -(zv - y[o]) * msk[o] * inv_d;
        out[o] = base_a * zv - bb * g_eps[o] + gs * gd;
    }
}

// ---------------- host driver ----------------
extern "C" void kernel_launch(void* const* d_in, const int* in_sizes, int n_in,
                              void* d_out, int out_size)
{
    const float* y   = (const float*)d_in[0];
    const float* msk = (const float*)d_in[1];
    const float* z0  = (const float*)d_in[2];
    const float* W1  = (const float*)d_in[3];
    const float* b1  = (const float*)d_in[4];
    const float* W2  = (const float*)d_in[5];
    const float* b2  = (const float*)d_in[6];
    const float* tw  = (const float*)d_in[7];

    static float ac[1000];
    {
        float run = 1.0f;
        for (int i = 0; i < 1000; i++) {
            float beta = 1e-4f + (0.02f - 1e-4f) * ((float)i / 999.0f);
            run *= (1.0f - beta);
            ac[i] = run;
        }
    }
    auto alpha_at = [&](int i) { return sqrtf(ac[i]); };
    auto sigma_at = [&](int i) { return sqrtf(1.0f - ac[i]); };
    auto lam_at   = [&](int i) { return logf(alpha_at(i)) - logf(sigma_at(i)); };

    float *p_h, *p_eps, *p_za, *p_zb;
    cudaGetSymbolAddress((void**)&p_h,   g_h);
    cudaGetSymbolAddress((void**)&p_eps, g_eps);
    cudaGetSymbolAddress((void**)&p_za,  g_za);
    cudaGetSymbolAddress((void**)&p_zb,  g_zb);
    __nv_bfloat16 *za0, *za1, *za2, *h0, *h1, *h2;
    __nv_bfloat16 *b1t0, *b1t1, *b1t2, *b2t0, *b2t1, *b2t2;
    cudaGetSymbolAddress((void**)&za0, g_za0);
    cudaGetSymbolAddress((void**)&za1, g_za1);
    cudaGetSymbolAddress((void**)&za2, g_za2);
    cudaGetSymbolAddress((void**)&h0,  g_h0);
    cudaGetSymbolAddress((void**)&h1,  g_h1);
    cudaGetSymbolAddress((void**)&h2,  g_h2);
    cudaGetSymbolAddress((void**)&b1t0, g_b1t0);
    cudaGetSymbolAddress((void**)&b1t1, g_b1t1);
    cudaGetSymbolAddress((void**)&b1t2, g_b1t2);
    cudaGetSymbolAddress((void**)&b2t0, g_b2t0);
    cudaGetSymbolAddress((void**)&b2t1, g_b2t1);
    cudaGetSymbolAddress((void**)&b2t2, g_b2t2);

    cudaFuncSetAttribute(gemm_mma<128, true >, cudaFuncAttributeMaxDynamicSharedMemorySize, SMEMB);
    cudaFuncSetAttribute(gemm_mma<512, false>, cudaFuncAttributeMaxDynamicSharedMemorySize, SMEMB);

    const float* zin[4]  = { z0,  p_za, p_zb, p_za };
    float*       zout[4] = { p_za, p_zb, p_za, (float*)d_out };

    prep_k<<<512, 256>>>(W1, W2);

    const int step = 1000 / 4;
    dim3 grid1(H_ / 128, M_ / 128);   // (4, 128)
    dim3 grid2(C_ / 128, M_ / 128);   // (1, 128)

    for (int si = 0; si < 4; si++) {
        int k  = 999 - si * step;
        int kp = k - step; if (kp < 0) kp = 0;
        float t_feat = (float)k / 1000.0f;
        float h_lam  = lam_at(kp) - lam_at(k);
        float base_a = alpha_at(kp) / alpha_at(k);
        float base_b = sigma_at(kp) * (expf(h_lam) - 1.0f);

        splitz_k<<<M_ * C_ / 1024, 256>>>(zin[si]);
        gemm_mma<128, true ><<<grid1, 256, SMEMB>>>(za0, za1, za2, b1t0, b1t1, b1t2,
                                                    b1, tw, t_feat, p_h, H_);
        splith_k<<<M_ * H_ / 1024, 256>>>();
        gemm_mma<512, false><<<grid2, 256, SMEMB>>>(h0, h1, h2, b2t0, b2t1, b2t2,
                                                    b2, b2, 0.0f, p_eps, C_);
        stats_k <<<LC_ / 256, 256>>>(zin[si], y, msk);
        pool_k  <<<168, 256>>>();
        select_k<<<5, 1024>>>();
        update_k<<<LC_ / 256, 256>>>(zin[si], y, msk, zout[si], base_a, base_b, h_lam);
    }
}

// round 7
// speedup vs baseline: 1.8343x; 1.8343x over previous
#include <cuda_runtime.h>
#include <cuda_bf16.h>
#include <math.h>
#include <stdint.h>

#define B_  16
#define L_  1024
#define C_  128
#define H_  512
#define LC_ (L_*C_)      // 131072
#define M_  (B_*L_)      // 16384

// ---------------- device scratch ----------------
__device__ float g_h  [M_*H_];        // 32 MB hidden activations (fp32)
__device__ float g_eps[M_*C_];
__device__ float g_za [M_*C_];
__device__ float g_zb [M_*C_];
__device__ float g_ent[LC_];
__device__ float g_p1[(L_/2)*(C_/2)];   // 32768
__device__ float g_p2[(L_/4)*(C_/4)];   // 8192
__device__ float g_p3[(L_/8)*(C_/8)];   // 2048
__device__ float g_part[1024];
__device__ float g_T[4];
__device__ float g_stats[2];
__device__ unsigned g_hist[4 * 65536];  // 1MB shared by both radix levels (zero-invariant)
__device__ unsigned g_pref[4];
__device__ unsigned g_krem[4];
// activation splits (bf16 x3)
__device__ __nv_bfloat16 g_za0[M_*C_], g_za1[M_*C_], g_za2[M_*C_];   // z  [16384,128]
__device__ __nv_bfloat16 g_h0 [M_*H_], g_h1 [M_*H_], g_h2 [M_*H_];   // h  [16384,512]
// weight splits, transposed [N,K] row-major (K contiguous)
__device__ __nv_bfloat16 g_b1t0[H_*C_], g_b1t1[H_*C_], g_b1t2[H_*C_]; // [512,128]
__device__ __nv_bfloat16 g_b2t0[C_*H_], g_b2t1[C_*H_], g_b2t2[C_*H_]; // [128,512]

__constant__ int c_K[4] = { 26214, 6553, 1638, 409 };   // int(0.2 * pooled.size)

// ---------------- helpers ----------------
__device__ __forceinline__ uint32_t smem_u32(const void* p) {
    uint32_t a;
    asm("{ .reg .u64 t; cvta.to.shared.u64 t, %1; cvt.u32.u64 %0, t; }" : "=r"(a) : "l"(p));
    return a;
}
__device__ __forceinline__ void cp_async16(uint32_t s, const void* g) {
    asm volatile("cp.async.cg.shared.global [%0], [%1], 16;" :: "r"(s), "l"(g) : "memory");
}
__device__ __forceinline__ void ldsm_x4(uint32_t* r, uint32_t addr) {
    asm volatile("ldmatrix.sync.aligned.m8n8.x4.shared.b16 {%0,%1,%2,%3}, [%4];"
                 : "=r"(r[0]), "=r"(r[1]), "=r"(r[2]), "=r"(r[3]) : "r"(addr));
}
__device__ __forceinline__ void mma16816(float* d, const uint32_t* a, const uint32_t* b) {
    asm volatile(
        "mma.sync.aligned.m16n8k16.row.col.f32.bf16.bf16.f32 "
        "{%0,%1,%2,%3}, {%4,%5,%6,%7}, {%8,%9}, {%0,%1,%2,%3};"
        : "+f"(d[0]), "+f"(d[1]), "+f"(d[2]), "+f"(d[3])
        : "r"(a[0]), "r"(a[1]), "r"(a[2]), "r"(a[3]), "r"(b[0]), "r"(b[1]));
}
__device__ __forceinline__ float gelu_f(float x) {
    float x3 = x * x * x;
    float u  = 0.7978845608028654f * (x + 0.044715f * x3);
    return 0.5f * x * (1.0f + tanhf(u));
}
__device__ __forceinline__ void split3(float x, unsigned short& h0, unsigned short& h1, unsigned short& h2) {
    __nv_bfloat16 b0 = __float2bfloat16_rn(x);
    float r1 = x - __bfloat162float(b0);
    __nv_bfloat16 b1 = __float2bfloat16_rn(r1);
    float r2 = r1 - __bfloat162float(b1);
    __nv_bfloat16 b2 = __float2bfloat16_rn(r2);
    h0 = __bfloat16_as_ushort(b0);
    h1 = __bfloat16_as_ushort(b1);
    h2 = __bfloat16_as_ushort(b2);
}

// ---------------- weight prep: transpose + 3-way split ------------------
__global__ __launch_bounds__(256) void prep_k(const float* __restrict__ W1, const float* __restrict__ W2)
{
    int t = blockIdx.x * 256 + threadIdx.x;   // 131072 total
    float x; int idx;
    __nv_bfloat16 *d0, *d1, *d2;
    if (t < H_ * C_) {                        // B1t [512,128] from W1[128,512]
        idx = t; int n = idx >> 7, k = idx & 127;
        x = W1[k * H_ + n];
        d0 = g_b1t0; d1 = g_b1t1; d2 = g_b1t2;
    } else {                                  // B2t [128,512] from W2[512,128]
        idx = t - H_ * C_; int n = idx >> 9, k = idx & 511;
        x = W2[k * C_ + n];
        d0 = g_b2t0; d1 = g_b2t1; d2 = g_b2t2;
    }
    unsigned short h0, h1, h2;
    split3(x, h0, h1, h2);
    d0[idx] = __ushort_as_bfloat16(h0);
    d1[idx] = __ushort_as_bfloat16(h1);
    d2[idx] = __ushort_as_bfloat16(h2);
}

// ---------------- streaming splitters (fp32 -> 3x bf16) ------------------
__global__ __launch_bounds__(256) void splitz_k(const float* __restrict__ src)
{
    int i = blockIdx.x * 256 + threadIdx.x;   // < M_*C_/4
    float4 v = *(const float4*)(src + (size_t)i * 4);
    float x[4] = { v.x, v.y, v.z, v.w };
    unsigned short s0[4], s1[4], s2[4];
#pragma unroll
    for (int j = 0; j < 4; j++) split3(x[j], s0[j], s1[j], s2[j]);
    ((uint2*)g_za0)[i] = make_uint2((uint32_t)s0[0] | ((uint32_t)s0[1] << 16), (uint32_t)s0[2] | ((uint32_t)s0[3] << 16));
    ((uint2*)g_za1)[i] = make_uint2((uint32_t)s1[0] | ((uint32_t)s1[1] << 16), (uint32_t)s1[2] | ((uint32_t)s1[3] << 16));
    ((uint2*)g_za2)[i] = make_uint2((uint32_t)s2[0] | ((uint32_t)s2[1] << 16), (uint32_t)s2[2] | ((uint32_t)s2[3] << 16));
}
__global__ __launch_bounds__(256) void splith_k()
{
    int i = blockIdx.x * 256 + threadIdx.x;   // < M_*H_/4
    float4 v = *(const float4*)(g_h + (size_t)i * 4);
    float x[4] = { v.x, v.y, v.z, v.w };
    unsigned short s0[4], s1[4], s2[4];
#pragma unroll
    for (int j = 0; j < 4; j++) split3(x[j], s0[j], s1[j], s2[j]);
    ((uint2*)g_h0)[i] = make_uint2((uint32_t)s0[0] | ((uint32_t)s0[1] << 16), (uint32_t)s0[2] | ((uint32_t)s0[3] << 16));
    ((uint2*)g_h1)[i] = make_uint2((uint32_t)s1[0] | ((uint32_t)s1[1] << 16), (uint32_t)s1[2] | ((uint32_t)s1[3] << 16));
    ((uint2*)g_h2)[i] = make_uint2((uint32_t)s2[0] | ((uint32_t)s2[1] << 16), (uint32_t)s2[2] | ((uint32_t)s2[3] << 16));
}

// ---------------- split-fp32 GEMM via bf16 mma.sync ---------------------
// 256 threads, 8 warps (64x32 warp tiles), CTA 128x128, BK=32, double-buffered.
static constexpr int TERMB = 10240;   // 128 rows x 80B (64B data + 16B pad)
static constexpr int BOFF  = 3 * TERMB;
static constexpr int BUFB  = 6 * TERMB;   // 61440
static constexpr int SMEMB = 2 * BUFB;    // 122880

template<int KTOT, bool GELU>
__global__ __launch_bounds__(256, 1)
void gemm_mma(const __nv_bfloat16* __restrict__ A0, const __nv_bfloat16* __restrict__ A1,
              const __nv_bfloat16* __restrict__ A2,
              const __nv_bfloat16* __restrict__ Bt0, const __nv_bfloat16* __restrict__ Bt1,
              const __nv_bfloat16* __restrict__ Bt2,
              const float* __restrict__ bias, const float* __restrict__ tw, float t_feat,
              float* __restrict__ out, int Ntot)
{
    extern __shared__ char smem[];
    const uint32_t sb = smem_u32(smem);
    const int tid = threadIdx.x, lane = tid & 31, wid = tid >> 5;
    const int m0 = blockIdx.y * 128, n0 = blockIdx.x * 128;
    const int wm = (wid >> 2) * 64, wn = (wid & 3) * 32;

    float acc[4][4][4];
#pragma unroll
    for (int a = 0; a < 4; a++)
#pragma unroll
        for (int b = 0; b < 4; b++)
#pragma unroll
            for (int c = 0; c < 4; c++) acc[a][b][c] = 0.0f;

    auto load_tile = [&](int kt, int buf) {
        uint32_t base = sb + buf * BUFB;
#pragma unroll
        for (int i = 0; i < 6; i++) {
            int rem = (i & 1) * 256 + tid;               // [0,512)
            int row = rem >> 2, ch = rem & 3;
            const __nv_bfloat16* src = (i < 2) ? A0 : ((i < 4) ? A1 : A2);  // compile-time per i
            cp_async16(base + (i >> 1) * TERMB + row * 80 + ch * 16,
                       src + (size_t)(m0 + row) * KTOT + kt * 32 + ch * 8);
        }
#pragma unroll
        for (int i = 0; i < 6; i++) {
            int rem = (i & 1) * 256 + tid;
            int row = rem >> 2, ch = rem & 3;
            const __nv_bfloat16* src = (i < 2) ? Bt0 : ((i < 4) ? Bt1 : Bt2);
            cp_async16(base + BOFF + (i >> 1) * TERMB + row * 80 + ch * 16,
                       src + (size_t)(n0 + row) * KTOT + kt * 32 + ch * 8);
        }
        asm volatile("cp.async.commit_group;" ::: "memory");
    };

    constexpr int NKT = KTOT / 32;
    load_tile(0, 0);
    int buf = 0;

    const int PA[6] = { 0, 0, 1, 1, 0, 2 };
    const int PB[6] = { 0, 1, 0, 1, 2, 0 };

#pragma unroll 1
    for (int kt = 0; kt < NKT; kt++) {
        if (kt + 1 < NKT) {
            load_tile(kt + 1, buf ^ 1);
            asm volatile("cp.async.wait_group 1;" ::: "memory");
        } else {
            asm volatile("cp.async.wait_group 0;" ::: "memory");
        }
        __syncthreads();

        uint32_t base = sb + buf * BUFB;
#pragma unroll
        for (int kk = 0; kk < 2; kk++) {
            uint32_t aF[3][4][4];
            uint32_t bF[3][4][2];
#pragma unroll
            for (int t = 0; t < 3; t++) {
#pragma unroll
                for (int mi = 0; mi < 4; mi++) {
                    uint32_t addr = base + t * TERMB
                        + (wm + mi * 16 + (lane & 15)) * 80
                        + kk * 32 + (lane >> 4) * 16;
                    ldsm_x4(aF[t][mi], addr);
                }
#pragma unroll
                for (int nt = 0; nt < 2; nt++) {
                    int row = wn + nt * 16 + ((lane >> 4) & 1) * 8 + (lane & 7);
                    uint32_t addr = base + BOFF + t * TERMB
                        + row * 80 + kk * 32 + ((lane >> 3) & 1) * 16;
                    uint32_t r[4];
                    ldsm_x4(r, addr);
                    bF[t][nt * 2][0]     = r[0]; bF[t][nt * 2][1]     = r[1];
                    bF[t][nt * 2 + 1][0] = r[2]; bF[t][nt * 2 + 1][1] = r[3];
                }
            }
#pragma unroll
            for (int p = 0; p < 6; p++) {
#pragma unroll
                for (int mi = 0; mi < 4; mi++)
#pragma unroll
                    for (int ni = 0; ni < 4; ni++)
                        mma16816(acc[mi][ni], aF[PA[p]][mi], bF[PB[p]][ni]);
            }
        }
        __syncthreads();
        buf ^= 1;
    }

    // ---- epilogue: bias (+time) (+gelu), fp32 float2 stores ----
#pragma unroll
    for (int mi = 0; mi < 4; mi++) {
#pragma unroll
        for (int ni = 0; ni < 4; ni++) {
            int r0 = m0 + wm + mi * 16 + (lane >> 2);
            int r1 = r0 + 8;
            int c  = n0 + wn + ni * 8 + (lane & 3) * 2;
            float bz0 = __ldg(bias + c);
            float bz1 = __ldg(bias + c + 1);
            if (GELU) { bz0 += t_feat * __ldg(tw + c); bz1 += t_feat * __ldg(tw + c + 1); }
            float v00 = acc[mi][ni][0] + bz0;
            float v01 = acc[mi][ni][1] + bz1;
            float v10 = acc[mi][ni][2] + bz0;
            float v11 = acc[mi][ni][3] + bz1;
            if (GELU) {
                v00 = gelu_f(v00); v01 = gelu_f(v01);
                v10 = gelu_f(v10); v11 = gelu_f(v11);
            }
            *(float2*)(out + (size_t)r0 * Ntot + c) = make_float2(v00, v01);
            *(float2*)(out + (size_t)r1 * Ntot + c) = make_float2(v10, v11);
        }
    }
}

// ---------------- entropy map + obs_err partial stats ----------------
__global__ __launch_bounds__(256)
void stats_k(const float* __restrict__ z, const float* __restrict__ y,
             const float* __restrict__ msk)
{
    int tid = threadIdx.x;
    int i = blockIdx.x * 256 + tid;

    float sa = 0.0f;
#pragma unroll
    for (int b = 0; b < B_; b++) sa += fabsf(g_eps[(size_t)b * LC_ + i]);
    g_ent[i] = sa * (1.0f / B_);

    float s = 0.0f, sq = 0.0f;
#pragma unroll
    for (int b = 0; b < B_; b++) {
        size_t o = (size_t)b * LC_ + i;
        float e = (z[o] - y[o]) * msk[o];
        s += e; sq += e * e;
    }
    __shared__ float rs[256], rq[256];
    rs[tid] = s; rq[tid] = sq;
    __syncthreads();
    for (int st = 128; st > 0; st >>= 1) {
        if (tid < st) { rs[tid] += rs[tid + st]; rq[tid] += rq[tid + st]; }
        __syncthreads();
    }
    if (tid == 0) { g_part[blockIdx.x] = rs[0]; g_part[512 + blockIdx.x] = rq[0]; }
}

// ---------------- hierarchical pooling ----------------
__global__ __launch_bounds__(256)
void pool_k()
{
    int t = blockIdx.x * 256 + threadIdx.x;
    int w, idx; float* dst;
    if      (t < 32768) { w = 2; dst = g_p1; idx = t; }
    else if (t < 40960) { w = 4; dst = g_p2; idx = t - 32768; }
    else if (t < 43008) { w = 8; dst = g_p3; idx = t - 40960; }
    else return;
    int Cs = C_ / w;
    int pr = idx / Cs, pc = idx % Cs;
    float s = 0.0f;
    for (int a = 0; a < w; a++)
        for (int b = 0; b < w; b++)
            s += g_ent[(pr * w + a) * C_ + pc * w + b];
    dst[idx] = s / (float)(w * w);
}

// ---------------- grid-parallel two-level radix select ----------------
// level selects 16 bits at a time via a 4x65536 global histogram; the scan
// kernels zero the histogram after reading so the buffer stays zero-invariant.
__device__ __forceinline__ const float* sel_elem(int g, int& s, int& i) {
    if (g < 131072)      { s = 0; i = g;          return g_ent; }
    else if (g < 163840) { s = 1; i = g - 131072; return g_p1;  }
    else if (g < 172032) { s = 2; i = g - 163840; return g_p2;  }
    else                 { s = 3; i = g - 172032; return g_p3;  }
}

__global__ __launch_bounds__(256)
void hist16_k()
{
    int g = blockIdx.x * 256 + threadIdx.x;   // < 174080
    int s, i;
    const float* d = sel_elem(g, s, i);
    unsigned u = __float_as_uint(d[i]);
    atomicAdd(&g_hist[s * 65536 + (u >> 16)], 1u);
}

__global__ __launch_bounds__(256)
void hist2_k()
{
    int g = blockIdx.x * 256 + threadIdx.x;
    int s, i;
    const float* d = sel_elem(g, s, i);
    unsigned u = __float_as_uint(d[i]);
    if ((u >> 16) == g_pref[s])
        atomicAdd(&g_hist[s * 65536 + (u & 0xFFFFu)], 1u);
}

// One block per scale. LEVEL=0: writes g_pref/g_krem. LEVEL=1: writes g_T.
// gridDim = 4 (level 0) or 5 (level 1; block 4 finalizes the variance stats).
template<int LEVEL>
__global__ __launch_bounds__(1024)
void scan_k()
{
    int s = blockIdx.x;
    int t = threadIdx.x;

    if (LEVEL == 1 && s == 4) {   // variance finalize
        __shared__ float rs[1024], rq[1024];
        rs[t] = (t < 512) ? g_part[t] : 0.0f;
        rq[t] = (t < 512) ? g_part[512 + t] : 0.0f;
        __syncthreads();
        for (int st = 512; st > 0; st >>= 1) {
            if (t < st) { rs[t] += rs[t + st]; rq[t] += rq[t + st]; }
            __syncthreads();
        }
        if (t == 0) { g_stats[0] = rs[0]; g_stats[1] = rq[0]; }
        return;
    }

    unsigned* h = g_hist + s * 65536;
    unsigned K = (LEVEL == 0) ? (unsigned)c_K[s] : g_krem[s];

    // per-thread chunk [t*64, t*64+64)
    unsigned p = 0;
#pragma unroll 8
    for (int j = 0; j < 64; j++) p += h[t * 64 + j];

    __shared__ unsigned ssA[1024], ssB[1024];
    ssA[t] = p;
    __syncthreads();
    // inclusive suffix sum over chunks (ss[t] = sum_{t'>=t} p[t'])
    unsigned* src = ssA; unsigned* dst = ssB;
#pragma unroll
    for (int off = 1; off < 1024; off <<= 1) {
        unsigned v = src[t] + ((t + off < 1024) ? src[t + off] : 0u);
        __syncthreads();
        dst[t] = v;
        __syncthreads();
        unsigned* tmp = src; src = dst; dst = tmp;
    }
    unsigned incl = src[t];
    unsigned above = incl - p;     // chunks strictly higher than t

    if (incl >= K && above < K) {  // crossing chunk (exactly one)
        unsigned cum = above;
        for (int j = 63; j >= 0; j--) {
            unsigned c = h[t * 64 + j];
            if (cum + c >= K) {
                unsigned bin = (unsigned)(t * 64 + j);
                if (LEVEL == 0) { g_pref[s] = bin; g_krem[s] = K - cum; }
                else            g_T[s] = __uint_as_float((g_pref[s] << 16) | bin);
                break;
            }
            cum += c;
        }
    }
    __syncthreads();
    // zero the histogram for reuse / next replay
#pragma unroll 8
    for (int j = 0; j < 64; j++) h[t * 64 + j] = 0u;
}

// ---------------- final update ----------------
__global__ __launch_bounds__(256)
void update_k(const float* __restrict__ z, const float* __restrict__ y,
              const float* __restrict__ msk, float* __restrict__ out,
              float base_a, float base_b, float h_lam)
{
    int i = blockIdx.x * 256 + threadIdx.x;
    int l = i / C_, c = i % C_;

    int sfound = -1; float ent = 0.0f;
    float v0 = g_ent[i];
    if (v0 >= g_T[0]) { sfound = 0; ent = v0; }
    else {
        float v1 = g_p1[(l >> 1) * (C_ / 2) + (c >> 1)];
        if (v1 >= g_T[1]) { sfound = 1; ent = v1; }
        else {
            float v2 = g_p2[(l >> 2) * (C_ / 4) + (c >> 2)];
            if (v2 >= g_T[2]) { sfound = 2; ent = v2; }
            else {
                float v3 = g_p3[(l >> 3) * (C_ / 8) + (c >> 3)];
                if (v3 >= g_T[3]) { sfound = 3; ent = v3; }
            }
        }
    }

    if (sfound < 0) {
#pragma unroll
        for (int b = 0; b < B_; b++) {
            size_t o = (size_t)b * LC_ + i;
            out[o] = z[o];
        }
        return;
    }

    const float invN = 1.0f / (float)(B_ * LC_);
    float mean = g_stats[0] * invN;
    float var  = g_stats[1] * invN - mean * mean;
    float inv_d = 1.0f / (var + 1e-8f);

    float om1 = (ent > 0.1f ? 1.0f : 0.0f) + (ent > 0.5f ? 1.0f : 0.0f);
    float corr = 1.0f + om1 * 0.5f * h_lam
               + om1 * (om1 - 1.0f) * (1.0f / 6.0f) * h_lam * h_lam;
    float gs = 2.0f * ent / (ent + 1.0f);
    float bb = base_b * corr;

#pragma unroll
    for (int b = 0; b < B_; b++) {
        size_t o = (size_t)b * LC_ + i;
        float zv = z[o];
        float gd = -(zv - y[o]) * msk[o] * inv_d;
        out[o] = base_a * zv - bb * g_eps[o] + gs * gd;
    }
}

// ---------------- host driver ----------------
extern "C" void kernel_launch(void* const* d_in, const int* in_sizes, int n_in,
                              void* d_out, int out_size)
{
    const float* y   = (const float*)d_in[0];
    const float* msk = (const float*)d_in[1];
    const float* z0  = (const float*)d_in[2];
    const float* W1  = (const float*)d_in[3];
    const float* b1  = (const float*)d_in[4];
    const float* W2  = (const float*)d_in[5];
    const float* b2  = (const float*)d_in[6];
    const float* tw  = (const float*)d_in[7];

    static float ac[1000];
    {
        float run = 1.0f;
        for (int i = 0; i < 1000; i++) {
            float beta = 1e-4f + (0.02f - 1e-4f) * ((float)i / 999.0f);
            run *= (1.0f - beta);
            ac[i] = run;
        }
    }
    auto alpha_at = [&](int i) { return sqrtf(ac[i]); };
    auto sigma_at = [&](int i) { return sqrtf(1.0f - ac[i]); };
    auto lam_at   = [&](int i) { return logf(alpha_at(i)) - logf(sigma_at(i)); };

    float *p_h, *p_eps, *p_za, *p_zb;
    cudaGetSymbolAddress((void**)&p_h,   g_h);
    cudaGetSymbolAddress((void**)&p_eps, g_eps);
    cudaGetSymbolAddress((void**)&p_za,  g_za);
    cudaGetSymbolAddress((void**)&p_zb,  g_zb);
    __nv_bfloat16 *za0, *za1, *za2, *h0, *h1, *h2;
    __nv_bfloat16 *b1t0, *b1t1, *b1t2, *b2t0, *b2t1, *b2t2;
    cudaGetSymbolAddress((void**)&za0, g_za0);
    cudaGetSymbolAddress((void**)&za1, g_za1);
    cudaGetSymbolAddress((void**)&za2, g_za2);
    cudaGetSymbolAddress((void**)&h0,  g_h0);
    cudaGetSymbolAddress((void**)&h1,  g_h1);
    cudaGetSymbolAddress((void**)&h2,  g_h2);
    cudaGetSymbolAddress((void**)&b1t0, g_b1t0);
    cudaGetSymbolAddress((void**)&b1t1, g_b1t1);
    cudaGetSymbolAddress((void**)&b1t2, g_b1t2);
    cudaGetSymbolAddress((void**)&b2t0, g_b2t0);
    cudaGetSymbolAddress((void**)&b2t1, g_b2t1);
    cudaGetSymbolAddress((void**)&b2t2, g_b2t2);

    cudaFuncSetAttribute(gemm_mma<128, true >, cudaFuncAttributeMaxDynamicSharedMemorySize, SMEMB);
    cudaFuncSetAttribute(gemm_mma<512, false>, cudaFuncAttributeMaxDynamicSharedMemorySize, SMEMB);

    const float* zin[4]  = { z0,  p_za, p_zb, p_za };
    float*       zout[4] = { p_za, p_zb, p_za, (float*)d_out };

    prep_k<<<512, 256>>>(W1, W2);

    const int step = 1000 / 4;
    dim3 grid1(H_ / 128, M_ / 128);   // (4, 128)
    dim3 grid2(C_ / 128, M_ / 128);   // (1, 128)

    for (int si = 0; si < 4; si++) {
        int k  = 999 - si * step;
        int kp = k - step; if (kp < 0) kp = 0;
        float t_feat = (float)k / 1000.0f;
        float h_lam  = lam_at(kp) - lam_at(k);
        float base_a = alpha_at(kp) / alpha_at(k);
        float base_b = sigma_at(kp) * (expf(h_lam) - 1.0f);

        splitz_k<<<M_ * C_ / 1024, 256>>>(zin[si]);
        gemm_mma<128, true ><<<grid1, 256, SMEMB>>>(za0, za1, za2, b1t0, b1t1, b1t2,
                                                    b1, tw, t_feat, p_h, H_);
        splith_k<<<M_ * H_ / 1024, 256>>>();
        gemm_mma<512, false><<<grid2, 256, SMEMB>>>(h0, h1, h2, b2t0, b2t1, b2t2,
                                                    b2, b2, 0.0f, p_eps, C_);
        stats_k <<<LC_ / 256, 256>>>(zin[si], y, msk);
        pool_k  <<<168, 256>>>();
        hist16_k<<<680, 256>>>();
        scan_k<0><<<4, 1024>>>();
        hist2_k <<<680, 256>>>();
        scan_k<1><<<5, 1024>>>();
        update_k<<<LC_ / 256, 256>>>(zin[si], y, msk, zout[si], base_a, base_b, h_lam);
    }
}

// round 8
// speedup vs baseline: 1.9090x; 1.0407x over previous
#include <cuda_runtime.h>
#include <cuda_bf16.h>
#include <math.h>
#include <stdint.h>

#define B_  16
#define L_  1024
#define C_  128
#define H_  512
#define LC_ (L_*C_)      // 131072
#define M_  (B_*L_)      // 16384

// ---------------- device scratch ----------------
__device__ float g_h  [M_*H_];        // 32 MB hidden activations (fp32)
__device__ float g_eps[M_*C_];
__device__ float g_za [M_*C_];
__device__ float g_zb [M_*C_];
__device__ float g_ent[LC_];
__device__ float g_p1[(L_/2)*(C_/2)];   // 32768
__device__ float g_p2[(L_/4)*(C_/4)];   // 8192
__device__ float g_p3[(L_/8)*(C_/8)];   // 2048
__device__ float g_part[1024];          // 128 used per half
__device__ float g_T[4];
__device__ float g_stats[2];
__device__ unsigned g_hist[4 * 65536];  // zero-invariant across replays
__device__ unsigned g_pref[4];
__device__ unsigned g_krem[4];
// weight splits, transposed [N,K] row-major (K contiguous)
__device__ __nv_bfloat16 g_b1t0[H_*C_], g_b1t1[H_*C_], g_b1t2[H_*C_]; // [512,128]
__device__ __nv_bfloat16 g_b2t0[C_*H_], g_b2t1[C_*H_], g_b2t2[C_*H_]; // [128,512]

__constant__ int c_K[4] = { 26214, 6553, 1638, 409 };   // int(0.2 * pooled.size)

// ---------------- helpers ----------------
__device__ __forceinline__ uint32_t smem_u32(const void* p) {
    uint32_t a;
    asm("{ .reg .u64 t; cvta.to.shared.u64 t, %1; cvt.u32.u64 %0, t; }" : "=r"(a) : "l"(p));
    return a;
}
__device__ __forceinline__ void cp_async16(uint32_t s, const void* g) {
    asm volatile("cp.async.cg.shared.global [%0], [%1], 16;" :: "r"(s), "l"(g) : "memory");
}
#define STS64v(addr, r0, r1) \
    asm volatile("st.shared.v2.b32 [%0], {%1,%2};" :: "r"(addr), "r"(r0), "r"(r1) : "memory")
__device__ __forceinline__ void ldsm_x4(uint32_t* r, uint32_t addr) {
    asm volatile("ldmatrix.sync.aligned.m8n8.x4.shared.b16 {%0,%1,%2,%3}, [%4];"
                 : "=r"(r[0]), "=r"(r[1]), "=r"(r[2]), "=r"(r[3]) : "r"(addr));
}
__device__ __forceinline__ void mma16816(float* d, const uint32_t* a, const uint32_t* b) {
    asm volatile(
        "mma.sync.aligned.m16n8k16.row.col.f32.bf16.bf16.f32 "
        "{%0,%1,%2,%3}, {%4,%5,%6,%7}, {%8,%9}, {%0,%1,%2,%3};"
        : "+f"(d[0]), "+f"(d[1]), "+f"(d[2]), "+f"(d[3])
        : "r"(a[0]), "r"(a[1]), "r"(a[2]), "r"(a[3]), "r"(b[0]), "r"(b[1]));
}
__device__ __forceinline__ float gelu_f(float x) {
    float x3 = x * x * x;
    float u  = 0.7978845608028654f * (x + 0.044715f * x3);
    return 0.5f * x * (1.0f + tanhf(u));
}
__device__ __forceinline__ void split3(float x, unsigned short& h0, unsigned short& h1, unsigned short& h2) {
    __nv_bfloat16 b0 = __float2bfloat16_rn(x);
    float r1 = x - __bfloat162float(b0);
    __nv_bfloat16 b1 = __float2bfloat16_rn(r1);
    float r2 = r1 - __bfloat162float(b1);
    __nv_bfloat16 b2 = __float2bfloat16_rn(r2);
    h0 = __bfloat16_as_ushort(b0);
    h1 = __bfloat16_as_ushort(b1);
    h2 = __bfloat16_as_ushort(b2);
}

// ---------------- weight prep: transpose + 3-way split ------------------
__global__ __launch_bounds__(256) void prep_k(const float* __restrict__ W1, const float* __restrict__ W2)
{
    int t = blockIdx.x * 256 + threadIdx.x;   // 131072 total
    float x; int idx;
    __nv_bfloat16 *d0, *d1, *d2;
    if (t < H_ * C_) {                        // B1t [512,128] from W1[128,512]
        idx = t; int n = idx >> 7, k = idx & 127;
        x = W1[k * H_ + n];
        d0 = g_b1t0; d1 = g_b1t1; d2 = g_b1t2;
    } else {                                  // B2t [128,512] from W2[512,128]
        idx = t - H_ * C_; int n = idx >> 9, k = idx & 511;
        x = W2[k * C_ + n];
        d0 = g_b2t0; d1 = g_b2t1; d2 = g_b2t2;
    }
    unsigned short h0, h1, h2;
    split3(x, h0, h1, h2);
    d0[idx] = __ushort_as_bfloat16(h0);
    d1[idx] = __ushort_as_bfloat16(h1);
    d2[idx] = __ushort_as_bfloat16(h2);
}

// ---------------- split-fp32 GEMM, A split in-loader --------------------
// C[M,Ntot] = A[M,KTOT](fp32) @ B[Ntot,KTOT]^T(pre-split bf16x3)
// 256 threads, 8 warps (64x32 warp tiles), CTA 128x128, BK=32, double-buffered.
static constexpr int TERMB  = 10240;        // 128 rows x 80B (64B data + 16B pad)
static constexpr int ABYTES = 2 * 3 * TERMB;   // A bf16 region (2 bufs x 3 terms)
static constexpr int SMEMB  = 2 * ABYTES;      // + B region, 122880 total

template<int KTOT, bool GELU>
__global__ __launch_bounds__(256, 1)
void gemm_mma(const float* __restrict__ A,
              const __nv_bfloat16* __restrict__ Bt0, const __nv_bfloat16* __restrict__ Bt1,
              const __nv_bfloat16* __restrict__ Bt2,
              const float* __restrict__ bias, const float* __restrict__ tw, float t_feat,
              float* __restrict__ out, int Ntot)
{
    extern __shared__ char smem[];
    const uint32_t sb = smem_u32(smem);
    const int tid = threadIdx.x, lane = tid & 31, wid = tid >> 5;
    const int m0 = blockIdx.y * 128, n0 = blockIdx.x * 128;
    const int wm = (wid >> 2) * 64, wn = (wid & 3) * 32;

    float acc[4][4][4];
#pragma unroll
    for (int a = 0; a < 4; a++)
#pragma unroll
        for (int b = 0; b < 4; b++)
#pragma unroll
            for (int c = 0; c < 4; c++) acc[a][b][c] = 0.0f;

    // A fp32 prefetch: 4 float4/thread covers 128x32
    float4 aR[4];
    auto ldgA = [&](int kt) {
#pragma unroll
        for (int i = 0; i < 4; i++) {
            int f = tid + i * 256;
            aR[i] = *(const float4*)(A + (size_t)(m0 + (f >> 3)) * KTOT + kt * 32 + (f & 7) * 4);
        }
    };
    auto stsA = [&](int buf) {
        uint32_t base = sb + buf * (3 * TERMB);
#pragma unroll
        for (int i = 0; i < 4; i++) {
            int f = tid + i * 256;
            float x[4] = { aR[i].x, aR[i].y, aR[i].z, aR[i].w };
            unsigned short s0[4], s1[4], s2[4];
#pragma unroll
            for (int j = 0; j < 4; j++) split3(x[j], s0[j], s1[j], s2[j]);
            uint32_t addr = base + (f >> 3) * 80 + (f & 7) * 8;
            STS64v(addr,             (uint32_t)s0[0] | ((uint32_t)s0[1] << 16),
                                     (uint32_t)s0[2] | ((uint32_t)s0[3] << 16));
            STS64v(addr + TERMB,     (uint32_t)s1[0] | ((uint32_t)s1[1] << 16),
                                     (uint32_t)s1[2] | ((uint32_t)s1[3] << 16));
            STS64v(addr + 2 * TERMB, (uint32_t)s2[0] | ((uint32_t)s2[1] << 16),
                                     (uint32_t)s2[2] | ((uint32_t)s2[3] << 16));
        }
    };
    auto cpB = [&](int kt, int buf) {
        uint32_t base = sb + ABYTES + buf * (3 * TERMB);
#pragma unroll
        for (int i = 0; i < 6; i++) {
            int rem = (i & 1) * 256 + tid;
            int row = rem >> 2, ch = rem & 3;
            const __nv_bfloat16* src = (i < 2) ? Bt0 : ((i < 4) ? Bt1 : Bt2);
            cp_async16(base + (i >> 1) * TERMB + row * 80 + ch * 16,
                       src + (size_t)(n0 + row) * KTOT + kt * 32 + ch * 8);
        }
        asm volatile("cp.async.commit_group;" ::: "memory");
    };

    constexpr int NKT = KTOT / 32;
    ldgA(0);
    cpB(0, 0);
    int buf = 0;

    const int PA[6] = { 0, 0, 1, 1, 0, 2 };
    const int PB[6] = { 0, 1, 0, 1, 2, 0 };

#pragma unroll 1
    for (int kt = 0; kt < NKT; kt++) {
        stsA(buf);
        if (kt + 1 < NKT) {
            cpB(kt + 1, buf ^ 1);
            ldgA(kt + 1);
            asm volatile("cp.async.wait_group 1;" ::: "memory");
        } else {
            asm volatile("cp.async.wait_group 0;" ::: "memory");
        }
        __syncthreads();

        uint32_t baseA = sb + buf * (3 * TERMB);
        uint32_t baseB = sb + ABYTES + buf * (3 * TERMB);
#pragma unroll
        for (int kk = 0; kk < 2; kk++) {
            uint32_t aF[3][4][4];
            uint32_t bF[3][4][2];
#pragma unroll
            for (int t = 0; t < 3; t++) {
#pragma unroll
                for (int mi = 0; mi < 4; mi++) {
                    uint32_t addr = baseA + t * TERMB
                        + (wm + mi * 16 + (lane & 15)) * 80
                        + kk * 32 + (lane >> 4) * 16;
                    ldsm_x4(aF[t][mi], addr);
                }
#pragma unroll
                for (int nt = 0; nt < 2; nt++) {
                    int row = wn + nt * 16 + ((lane >> 4) & 1) * 8 + (lane & 7);
                    uint32_t addr = baseB + t * TERMB
                        + row * 80 + kk * 32 + ((lane >> 3) & 1) * 16;
                    uint32_t r[4];
                    ldsm_x4(r, addr);
                    bF[t][nt * 2][0]     = r[0]; bF[t][nt * 2][1]     = r[1];
                    bF[t][nt * 2 + 1][0] = r[2]; bF[t][nt * 2 + 1][1] = r[3];
                }
            }
#pragma unroll
            for (int p = 0; p < 6; p++) {
#pragma unroll
                for (int mi = 0; mi < 4; mi++)
#pragma unroll
                    for (int ni = 0; ni < 4; ni++)
                        mma16816(acc[mi][ni], aF[PA[p]][mi], bF[PB[p]][ni]);
            }
        }
        __syncthreads();
        buf ^= 1;
    }

    // ---- epilogue: bias (+time) (+gelu), fp32 float2 stores ----
#pragma unroll
    for (int mi = 0; mi < 4; mi++) {
#pragma unroll
        for (int ni = 0; ni < 4; ni++) {
            int r0 = m0 + wm + mi * 16 + (lane >> 2);
            int r1 = r0 + 8;
            int c  = n0 + wn + ni * 8 + (lane & 3) * 2;
            float bz0 = __ldg(bias + c);
            float bz1 = __ldg(bias + c + 1);
            if (GELU) { bz0 += t_feat * __ldg(tw + c); bz1 += t_feat * __ldg(tw + c + 1); }
            float v00 = acc[mi][ni][0] + bz0;
            float v01 = acc[mi][ni][1] + bz1;
            float v10 = acc[mi][ni][2] + bz0;
            float v11 = acc[mi][ni][3] + bz1;
            if (GELU) {
                v00 = gelu_f(v00); v01 = gelu_f(v01);
                v10 = gelu_f(v10); v11 = gelu_f(v11);
            }
            *(float2*)(out + (size_t)r0 * Ntot + c) = make_float2(v00, v01);
            *(float2*)(out + (size_t)r1 * Ntot + c) = make_float2(v10, v11);
        }
    }
}

// ---------------- fused: entropy + obs_err partials + pooling + hist16 ---
// 128 blocks x 256 threads; block owns 8 L-rows x 128 C (1024 pixels).
__global__ __launch_bounds__(256)
void fstats_k(const float* __restrict__ z, const float* __restrict__ y,
              const float* __restrict__ msk)
{
    int blk = blockIdx.x;
    int tid = threadIdx.x;
    __shared__ float ent_s[1024];
    __shared__ float rs[256], rq[256];

    float ps = 0.0f, pq = 0.0f;
#pragma unroll
    for (int j = 0; j < 4; j++) {
        int p = blk * 1024 + tid + j * 256;
        float sa = 0.0f;
#pragma unroll
        for (int b = 0; b < B_; b++) sa += fabsf(g_eps[(size_t)b * LC_ + p]);
        float e = sa * (1.0f / B_);
        g_ent[p] = e;
        ent_s[tid + j * 256] = e;
        atomicAdd(&g_hist[__float_as_uint(e) >> 16], 1u);
#pragma unroll
        for (int b = 0; b < B_; b++) {
            size_t o = (size_t)b * LC_ + p;
            float t = (z[o] - y[o]) * msk[o];
            ps += t; pq += t * t;
        }
    }
    rs[tid] = ps; rq[tid] = pq;
    __syncthreads();
    for (int st = 128; st > 0; st >>= 1) {
        if (tid < st) { rs[tid] += rs[tid + st]; rq[tid] += rq[tid + st]; }
        __syncthreads();
    }
    if (tid == 0) { g_part[blk] = rs[0]; g_part[512 + blk] = rq[0]; }

    // pooling from ent_s (local tile: 8 rows x 128 cols)
    {   // w=2: 4x64 = 256 entries, one per thread
        int pr = tid >> 6, pc = tid & 63;
        float s = 0.0f;
        for (int a = 0; a < 2; a++)
            for (int b = 0; b < 2; b++)
                s += ent_s[(pr * 2 + a) * 128 + pc * 2 + b];
        float v = s * 0.25f;
        g_p1[(blk * 4 + pr) * 64 + pc] = v;
        atomicAdd(&g_hist[65536 + (__float_as_uint(v) >> 16)], 1u);
    }
    if (tid < 64) {  // w=4: 2x32
        int pr = tid >> 5, pc = tid & 31;
        float s = 0.0f;
        for (int a = 0; a < 4; a++)
            for (int b = 0; b < 4; b++)
                s += ent_s[(pr * 4 + a) * 128 + pc * 4 + b];
        float v = s * (1.0f / 16.0f);
        g_p2[(blk * 2 + pr) * 32 + pc] = v;
        atomicAdd(&g_hist[2 * 65536 + (__float_as_uint(v) >> 16)], 1u);
    }
    if (tid < 16) {  // w=8: 1x16
        float s = 0.0f;
        for (int a = 0; a < 8; a++)
            for (int b = 0; b < 8; b++)
                s += ent_s[a * 128 + tid * 8 + b];
        float v = s * (1.0f / 64.0f);
        g_p3[blk * 16 + tid] = v;
        atomicAdd(&g_hist[3 * 65536 + (__float_as_uint(v) >> 16)], 1u);
    }
}

// ---------------- grid-parallel two-level radix select ----------------
__device__ __forceinline__ const float* sel_elem(int g, int& s, int& i) {
    if (g < 131072)      { s = 0; i = g;          return g_ent; }
    else if (g < 163840) { s = 1; i = g - 131072; return g_p1;  }
    else if (g < 172032) { s = 2; i = g - 163840; return g_p2;  }
    else                 { s = 3; i = g - 172032; return g_p3;  }
}

__global__ __launch_bounds__(256)
void hist2_k()
{
    int g = blockIdx.x * 256 + threadIdx.x;
    int s, i;
    const float* d = sel_elem(g, s, i);
    unsigned u = __float_as_uint(d[i]);
    if ((u >> 16) == g_pref[s])
        atomicAdd(&g_hist[s * 65536 + (u & 0xFFFFu)], 1u);
}

// One block per scale. LEVEL=0: writes g_pref/g_krem. LEVEL=1: writes g_T.
template<int LEVEL>
__global__ __launch_bounds__(1024)
void scan_k()
{
    int s = blockIdx.x;
    int t = threadIdx.x;

    if (LEVEL == 1 && s == 4) {   // variance finalize (128 block partials)
        __shared__ float rs[128], rq[128];
        if (t < 128) { rs[t] = g_part[t]; rq[t] = g_part[512 + t]; }
        __syncthreads();
        for (int st = 64; st > 0; st >>= 1) {
            if (t < st) { rs[t] += rs[t + st]; rq[t] += rq[t + st]; }
            __syncthreads();
        }
        if (t == 0) { g_stats[0] = rs[0]; g_stats[1] = rq[0]; }
        return;
    }

    unsigned* h = g_hist + s * 65536;
    unsigned K = (LEVEL == 0) ? (unsigned)c_K[s] : g_krem[s];

    unsigned p = 0;
#pragma unroll 8
    for (int j = 0; j < 64; j++) p += h[t * 64 + j];

    __shared__ unsigned ssA[1024], ssB[1024];
    ssA[t] = p;
    __syncthreads();
    unsigned* src = ssA; unsigned* dst = ssB;
#pragma unroll
    for (int off = 1; off < 1024; off <<= 1) {
        unsigned v = src[t] + ((t + off < 1024) ? src[t + off] : 0u);
        __syncthreads();
        dst[t] = v;
        __syncthreads();
        unsigned* tmp = src; src = dst; dst = tmp;
    }
    unsigned incl = src[t];
    unsigned above = incl - p;

    if (incl >= K && above < K) {
        unsigned cum = above;
        for (int j = 63; j >= 0; j--) {
            unsigned c = h[t * 64 + j];
            if (cum + c >= K) {
                unsigned bin = (unsigned)(t * 64 + j);
                if (LEVEL == 0) { g_pref[s] = bin; g_krem[s] = K - cum; }
                else            g_T[s] = __uint_as_float((g_pref[s] << 16) | bin);
                break;
            }
            cum += c;
        }
    }
    __syncthreads();
#pragma unroll 8
    for (int j = 0; j < 64; j++) h[t * 64 + j] = 0u;
}

// ---------------- final update ----------------
__global__ __launch_bounds__(256)
void update_k(const float* __restrict__ z, const float* __restrict__ y,
              const float* __restrict__ msk, float* __restrict__ out,
              float base_a, float base_b, float h_lam)
{
    int i = blockIdx.x * 256 + threadIdx.x;
    int l = i / C_, c = i % C_;

    int sfound = -1; float ent = 0.0f;
    float v0 = g_ent[i];
    if (v0 >= g_T[0]) { sfound = 0; ent = v0; }
    else {
        float v1 = g_p1[(l >> 1) * (C_ / 2) + (c >> 1)];
        if (v1 >= g_T[1]) { sfound = 1; ent = v1; }
        else {
            float v2 = g_p2[(l >> 2) * (C_ / 4) + (c >> 2)];
            if (v2 >= g_T[2]) { sfound = 2; ent = v2; }
            else {
                float v3 = g_p3[(l >> 3) * (C_ / 8) + (c >> 3)];
                if (v3 >= g_T[3]) { sfound = 3; ent = v3; }
            }
        }
    }

    if (sfound < 0) {
#pragma unroll
        for (int b = 0; b < B_; b++) {
            size_t o = (size_t)b * LC_ + i;
            out[o] = z[o];
        }
        return;
    }

    const float invN = 1.0f / (float)(B_ * LC_);
    float mean = g_stats[0] * invN;
    float var  = g_stats[1] * invN - mean * mean;
    float inv_d = 1.0f / (var + 1e-8f);

    float om1 = (ent > 0.1f ? 1.0f : 0.0f) + (ent > 0.5f ? 1.0f : 0.0f);
    float corr = 1.0f + om1 * 0.5f * h_lam
               + om1 * (om1 - 1.0f) * (1.0f / 6.0f) * h_lam * h_lam;
    float gs = 2.0f * ent / (ent + 1.0f);
    float bb = base_b * corr;

#pragma unroll
    for (int b = 0; b < B_; b++) {
        size_t o = (size_t)b * LC_ + i;
        float zv = z[o];
        float gd = -(zv - y[o]) * msk[o] * inv_d;
        out[o] = base_a * zv - bb * g_eps[o] + gs * gd;
    }
}

// ---------------- host driver ----------------
extern "C" void kernel_launch(void* const* d_in, const int* in_sizes, int n_in,
                              void* d_out, int out_size)
{
    const float* y   = (const float*)d_in[0];
    const float* msk = (const float*)d_in[1];
    const float* z0  = (const float*)d_in[2];
    const float* W1  = (const float*)d_in[3];
    const float* b1  = (const float*)d_in[4];
    const float* W2  = (const float*)d_in[5];
    const float* b2  = (const float*)d_in[6];
    const float* tw  = (const float*)d_in[7];

    static float ac[1000];
    {
        float run = 1.0f;
        for (int i = 0; i < 1000; i++) {
            float beta = 1e-4f + (0.02f - 1e-4f) * ((float)i / 999.0f);
            run *= (1.0f - beta);
            ac[i] = run;
        }
    }
    auto alpha_at = [&](int i) { return sqrtf(ac[i]); };
    auto sigma_at = [&](int i) { return sqrtf(1.0f - ac[i]); };
    auto lam_at   = [&](int i) { return logf(alpha_at(i)) - logf(sigma_at(i)); };

    float *p_h, *p_eps, *p_za, *p_zb;
    cudaGetSymbolAddress((void**)&p_h,   g_h);
    cudaGetSymbolAddress((void**)&p_eps, g_eps);
    cudaGetSymbolAddress((void**)&p_za,  g_za);
    cudaGetSymbolAddress((void**)&p_zb,  g_zb);
    __nv_bfloat16 *b1t0, *b1t1, *b1t2, *b2t0, *b2t1, *b2t2;
    cudaGetSymbolAddress((void**)&b1t0, g_b1t0);
    cudaGetSymbolAddress((void**)&b1t1, g_b1t1);
    cudaGetSymbolAddress((void**)&b1t2, g_b1t2);
    cudaGetSymbolAddress((void**)&b2t0, g_b2t0);
    cudaGetSymbolAddress((void**)&b2t1, g_b2t1);
    cudaGetSymbolAddress((void**)&b2t2, g_b2t2);

    cudaFuncSetAttribute(gemm_mma<128, true >, cudaFuncAttributeMaxDynamicSharedMemorySize, SMEMB);
    cudaFuncSetAttribute(gemm_mma<512, false>, cudaFuncAttributeMaxDynamicSharedMemorySize, SMEMB);

    const float* zin[4]  = { z0,  p_za, p_zb, p_za };
    float*       zout[4] = { p_za, p_zb, p_za, (float*)d_out };

    prep_k<<<512, 256>>>(W1, W2);

    const int step = 1000 / 4;
    dim3 grid1(H_ / 128, M_ / 128);   // (4, 128)
    dim3 grid2(C_ / 128, M_ / 128);   // (1, 128)

    for (int si = 0; si < 4; si++) {
        int k  = 999 - si * step;
        int kp = k - step; if (kp < 0) kp = 0;
        float t_feat = (float)k / 1000.0f;
        float h_lam  = lam_at(kp) - lam_at(k);
        float base_a = alpha_at(kp) / alpha_at(k);
        float base_b = sigma_at(kp) * (expf(h_lam) - 1.0f);

        gemm_mma<128, true ><<<grid1, 256, SMEMB>>>(zin[si], b1t0, b1t1, b1t2,
                                                    b1, tw, t_feat, p_h, H_);
        gemm_mma<512, false><<<grid2, 256, SMEMB>>>(p_h, b2t0, b2t1, b2t2,
                                                    b2, b2, 0.0f, p_eps, C_);
        fstats_k<<<128, 256>>>(zin[si], y, msk);
        scan_k<0><<<4, 1024>>>();
        hist2_k <<<680, 256>>>();
        scan_k<1><<<5, 1024>>>();
        update_k<<<LC_ / 256, 256>>>(zin[si], y, msk, zout[si], base_a, base_b, h_lam);
    }
}

// round 10
// speedup vs baseline: 1.9372x; 1.0148x over previous
#include <cuda_runtime.h>
#include <cuda_bf16.h>
#include <math.h>
#include <stdint.h>

#define B_  16
#define L_  1024
#define C_  128
#define H_  512
#define LC_ (L_*C_)      // 131072
#define M_  (B_*L_)      // 16384

// ---------------- device scratch ----------------
__device__ float g_h  [M_*H_];        // 32 MB hidden activations (fp32)
__device__ float g_eps[M_*C_];
__device__ float g_za [M_*C_];
__device__ float g_zb [M_*C_];
__device__ float g_ent[LC_];
__device__ float g_p1[(L_/2)*(C_/2)];   // 32768
__device__ float g_p2[(L_/4)*(C_/4)];   // 8192
__device__ float g_p3[(L_/8)*(C_/8)];   // 2048
__device__ float g_part[1024];          // 128 used per half
__device__ float g_T[4];
__device__ float g_stats[2];
__device__ unsigned g_hist[4 * 65536];  // zero-invariant across replays
__device__ unsigned g_pref[4];
__device__ unsigned g_krem[4];
// weight splits (3-term), transposed [N,K] row-major (K contiguous)
__device__ __nv_bfloat16 g_b1t0[H_*C_], g_b1t1[H_*C_], g_b1t2[H_*C_]; // [512,128]
__device__ __nv_bfloat16 g_b2t0[C_*H_], g_b2t1[C_*H_], g_b2t2[C_*H_]; // [128,512]

__constant__ int c_K[4] = { 26214, 6553, 1638, 409 };   // int(0.2 * pooled.size)

// ---------------- helpers ----------------
__device__ __forceinline__ uint32_t smem_u32(const void* p) {
    uint32_t a;
    asm("{ .reg .u64 t; cvta.to.shared.u64 t, %1; cvt.u32.u64 %0, t; }" : "=r"(a) : "l"(p));
    return a;
}
__device__ __forceinline__ void cp_async16(uint32_t s, const void* g) {
    asm volatile("cp.async.cg.shared.global [%0], [%1], 16;" :: "r"(s), "l"(g) : "memory");
}
#define STS64v(addr, r0, r1) \
    asm volatile("st.shared.v2.b32 [%0], {%1,%2};" :: "r"(addr), "r"(r0), "r"(r1) : "memory")
__device__ __forceinline__ void ldsm_x4(uint32_t* r, uint32_t addr) {
    asm volatile("ldmatrix.sync.aligned.m8n8.x4.shared.b16 {%0,%1,%2,%3}, [%4];"
                 : "=r"(r[0]), "=r"(r[1]), "=r"(r[2]), "=r"(r[3]) : "r"(addr));
}
__device__ __forceinline__ void mma16816(float* d, const uint32_t* a, const uint32_t* b) {
    asm volatile(
        "mma.sync.aligned.m16n8k16.row.col.f32.bf16.bf16.f32 "
        "{%0,%1,%2,%3}, {%4,%5,%6,%7}, {%8,%9}, {%0,%1,%2,%3};"
        : "+f"(d[0]), "+f"(d[1]), "+f"(d[2]), "+f"(d[3])
        : "r"(a[0]), "r"(a[1]), "r"(a[2]), "r"(a[3]), "r"(b[0]), "r"(b[1]));
}
// gelu(x) = x * sigmoid(2u) = x * rcp(1 + 2^(-2u*log2e)); exactly 2 MUFU, no branch.
__device__ __forceinline__ float gelu_f(float x) {
    float x2 = x * x;
    float u  = 0.7978845608028654f * x + 0.035677408136300125f * x * x2;
    float e, r;
    asm("ex2.approx.f32 %0, %1;" : "=f"(e) : "f"(-2.8853900817779268f * u));
    asm("rcp.approx.f32 %0, %1;" : "=f"(r) : "f"(1.0f + e));
    return x * r;
}
__device__ __forceinline__ void split3(float x, unsigned short& h0, unsigned short& h1, unsigned short& h2) {
    __nv_bfloat16 b0 = __float2bfloat16_rn(x);
    float r1 = x - __bfloat162float(b0);
    __nv_bfloat16 b1 = __float2bfloat16_rn(r1);
    float r2 = r1 - __bfloat162float(b1);
    __nv_bfloat16 b2 = __float2bfloat16_rn(r2);
    h0 = __bfloat16_as_ushort(b0);
    h1 = __bfloat16_as_ushort(b1);
    h2 = __bfloat16_as_ushort(b2);
}

// ---------------- weight prep: transpose + 3-way split ------------------
__global__ __launch_bounds__(256) void prep_k(const float* __restrict__ W1, const float* __restrict__ W2)
{
    int t = blockIdx.x * 256 + threadIdx.x;   // 131072 total
    float x; int idx;
    __nv_bfloat16 *d0, *d1, *d2;
    if (t < H_ * C_) {                        // B1t [512,128] from W1[128,512]
        idx = t; int n = idx >> 7, k = idx & 127;
        x = W1[k * H_ + n];
        d0 = g_b1t0; d1 = g_b1t1; d2 = g_b1t2;
    } else {                                  // B2t [128,512] from W2[512,128]
        idx = t - H_ * C_; int n = idx >> 9, k = idx & 511;
        x = W2[k * C_ + n];
        d0 = g_b2t0; d1 = g_b2t1; d2 = g_b2t2;
    }
    unsigned short h0, h1, h2;
    split3(x, h0, h1, h2);
    d0[idx] = __ushort_as_bfloat16(h0);
    d1[idx] = __ushort_as_bfloat16(h1);
    d2[idx] = __ushort_as_bfloat16(h2);
}

// ---------------- split-fp32 GEMM, A split in-loader (3-term, 6 passes) --
// C[M,Ntot] = A[M,KTOT](fp32) @ B[Ntot,KTOT]^T(pre-split bf16x3)
// 256 threads, 8 warps (64x32 warp tiles), CTA 128x128, BK=32, double-buffered.
static constexpr int TERMB  = 10240;           // 128 rows x 80B (64B data + 16B pad)
static constexpr int ABYTES = 2 * 3 * TERMB;   // A bf16 region (2 bufs x 3 terms)
static constexpr int SMEMB  = 2 * ABYTES;      // + B region, 122880 total

template<int KTOT, bool GELU>
__global__ __launch_bounds__(256, 1)
void gemm_mma(const float* __restrict__ A,
              const __nv_bfloat16* __restrict__ Bt0, const __nv_bfloat16* __restrict__ Bt1,
              const __nv_bfloat16* __restrict__ Bt2,
              const float* __restrict__ bias, const float* __restrict__ tw, float t_feat,
              float* __restrict__ out, int Ntot)
{
    extern __shared__ char smem[];
    const uint32_t sb = smem_u32(smem);
    const int tid = threadIdx.x, lane = tid & 31, wid = tid >> 5;
    const int m0 = blockIdx.y * 128, n0 = blockIdx.x * 128;
    const int wm = (wid >> 2) * 64, wn = (wid & 3) * 32;

    float acc[4][4][4];
#pragma unroll
    for (int a = 0; a < 4; a++)
#pragma unroll
        for (int b = 0; b < 4; b++)
#pragma unroll
            for (int c = 0; c < 4; c++) acc[a][b][c] = 0.0f;

    // A fp32 prefetch: 4 float4/thread covers 128x32
    float4 aR[4];
    auto ldgA = [&](int kt) {
#pragma unroll
        for (int i = 0; i < 4; i++) {
            int f = tid + i * 256;
            aR[i] = *(const float4*)(A + (size_t)(m0 + (f >> 3)) * KTOT + kt * 32 + (f & 7) * 4);
        }
    };
    auto stsA = [&](int buf) {
        uint32_t base = sb + buf * (3 * TERMB);
#pragma unroll
        for (int i = 0; i < 4; i++) {
            int f = tid + i * 256;
            float x[4] = { aR[i].x, aR[i].y, aR[i].z, aR[i].w };
            unsigned short s0[4], s1[4], s2[4];
#pragma unroll
            for (int j = 0; j < 4; j++) split3(x[j], s0[j], s1[j], s2[j]);
            uint32_t addr = base + (f >> 3) * 80 + (f & 7) * 8;
            STS64v(addr,             (uint32_t)s0[0] | ((uint32_t)s0[1] << 16),
                                     (uint32_t)s0[2] | ((uint32_t)s0[3] << 16));
            STS64v(addr + TERMB,     (uint32_t)s1[0] | ((uint32_t)s1[1] << 16),
                                     (uint32_t)s1[2] | ((uint32_t)s1[3] << 16));
            STS64v(addr + 2 * TERMB, (uint32_t)s2[0] | ((uint32_t)s2[1] << 16),
                                     (uint32_t)s2[2] | ((uint32_t)s2[3] << 16));
        }
    };
    auto cpB = [&](int kt, int buf) {
        uint32_t base = sb + ABYTES + buf * (3 * TERMB);
#pragma unroll
        for (int i = 0; i < 6; i++) {
            int rem = (i & 1) * 256 + tid;
            int row = rem >> 2, ch = rem & 3;
            const __nv_bfloat16* src = (i < 2) ? Bt0 : ((i < 4) ? Bt1 : Bt2);
            cp_async16(base + (i >> 1) * TERMB + row * 80 + ch * 16,
                       src + (size_t)(n0 + row) * KTOT + kt * 32 + ch * 8);
        }
        asm volatile("cp.async.commit_group;" ::: "memory");
    };

    constexpr int NKT = KTOT / 32;
    ldgA(0);
    cpB(0, 0);
    int buf = 0;

    const int PA[6] = { 0, 0, 1, 1, 0, 2 };
    const int PB[6] = { 0, 1, 0, 1, 2, 0 };

#pragma unroll 1
    for (int kt = 0; kt < NKT; kt++) {
        stsA(buf);
        if (kt + 1 < NKT) {
            cpB(kt + 1, buf ^ 1);
            ldgA(kt + 1);
            asm volatile("cp.async.wait_group 1;" ::: "memory");
        } else {
            asm volatile("cp.async.wait_group 0;" ::: "memory");
        }
        __syncthreads();

        uint32_t baseA = sb + buf * (3 * TERMB);
        uint32_t baseB = sb + ABYTES + buf * (3 * TERMB);
#pragma unroll
        for (int kk = 0; kk < 2; kk++) {
            uint32_t aF[3][4][4];
            uint32_t bF[3][4][2];
#pragma unroll
            for (int t = 0; t < 3; t++) {
#pragma unroll
                for (int mi = 0; mi < 4; mi++) {
                    uint32_t addr = baseA + t * TERMB
                        + (wm + mi * 16 + (lane & 15)) * 80
                        + kk * 32 + (lane >> 4) * 16;
                    ldsm_x4(aF[t][mi], addr);
                }
#pragma unroll
                for (int nt = 0; nt < 2; nt++) {
                    int row = wn + nt * 16 + ((lane >> 4) & 1) * 8 + (lane & 7);
                    uint32_t addr = baseB + t * TERMB
                        + row * 80 + kk * 32 + ((lane >> 3) & 1) * 16;
                    uint32_t r[4];
                    ldsm_x4(r, addr);
                    bF[t][nt * 2][0]     = r[0]; bF[t][nt * 2][1]     = r[1];
                    bF[t][nt * 2 + 1][0] = r[2]; bF[t][nt * 2 + 1][1] = r[3];
                }
            }
#pragma unroll
            for (int p = 0; p < 6; p++) {
#pragma unroll
                for (int mi = 0; mi < 4; mi++)
#pragma unroll
                    for (int ni = 0; ni < 4; ni++)
                        mma16816(acc[mi][ni], aF[PA[p]][mi], bF[PB[p]][ni]);
            }
        }
        __syncthreads();
        buf ^= 1;
    }

    // ---- epilogue: bias (+time) (+gelu), fp32 float2 stores ----
#pragma unroll
    for (int mi = 0; mi < 4; mi++) {
#pragma unroll
        for (int ni = 0; ni < 4; ni++) {
            int r0 = m0 + wm + mi * 16 + (lane >> 2);
            int r1 = r0 + 8;
            int c  = n0 + wn + ni * 8 + (lane & 3) * 2;
            float bz0 = __ldg(bias + c);
            float bz1 = __ldg(bias + c + 1);
            if (GELU) { bz0 += t_feat * __ldg(tw + c); bz1 += t_feat * __ldg(tw + c + 1); }
            float v00 = acc[mi][ni][0] + bz0;
            float v01 = acc[mi][ni][1] + bz1;
            float v10 = acc[mi][ni][2] + bz0;
            float v11 = acc[mi][ni][3] + bz1;
            if (GELU) {
                v00 = gelu_f(v00); v01 = gelu_f(v01);
                v10 = gelu_f(v10); v11 = gelu_f(v11);
            }
            *(float2*)(out + (size_t)r0 * Ntot + c) = make_float2(v00, v01);
            *(float2*)(out + (size_t)r1 * Ntot + c) = make_float2(v10, v11);
        }
    }
}

// ---------------- fused: entropy + obs_err partials + pooling + hist16 ---
// 128 blocks x 1024 threads; block owns 8 L-rows x 128 C (1024 pixels).
__global__ __launch_bounds__(1024)
void fstats_k(const float* __restrict__ z, const float* __restrict__ y,
              const float* __restrict__ msk)
{
    int blk = blockIdx.x;
    int tid = threadIdx.x;
    __shared__ float ent_s[1024];
    __shared__ float rs[1024], rq[1024];

    int p = blk * 1024 + tid;
    float sa = 0.0f;
#pragma unroll
    for (int b = 0; b < B_; b++) sa += fabsf(g_eps[(size_t)b * LC_ + p]);
    float e = sa * (1.0f / B_);
    g_ent[p] = e;
    ent_s[tid] = e;
    atomicAdd(&g_hist[__float_as_uint(e) >> 16], 1u);

    float ps = 0.0f, pq = 0.0f;
#pragma unroll
    for (int b = 0; b < B_; b++) {
        size_t o = (size_t)b * LC_ + p;
        float t = (z[o] - y[o]) * msk[o];
        ps += t; pq += t * t;
    }
    rs[tid] = ps; rq[tid] = pq;
    __syncthreads();
    for (int st = 512; st > 0; st >>= 1) {
        if (tid < st) { rs[tid] += rs[tid + st]; rq[tid] += rq[tid + st]; }
        __syncthreads();
    }
    if (tid == 0) { g_part[blk] = rs[0]; g_part[512 + blk] = rq[0]; }

    // pooling from ent_s (local tile: 8 rows x 128 cols)
    if (tid < 256) {   // w=2: 4x64
        int pr = tid >> 6, pc = tid & 63;
        float s = 0.0f;
        for (int a = 0; a < 2; a++)
            for (int b = 0; b < 2; b++)
                s += ent_s[(pr * 2 + a) * 128 + pc * 2 + b];
        float v = s * 0.25f;
        g_p1[(blk * 4 + pr) * 64 + pc] = v;
        atomicAdd(&g_hist[65536 + (__float_as_uint(v) >> 16)], 1u);
    }
    if (tid < 64) {  // w=4: 2x32
        int pr = tid >> 5, pc = tid & 31;
        float s = 0.0f;
        for (int a = 0; a < 4; a++)
            for (int b = 0; b < 4; b++)
                s += ent_s[(pr * 4 + a) * 128 + pc * 4 + b];
        float v = s * (1.0f / 16.0f);
        g_p2[(blk * 2 + pr) * 32 + pc] = v;
        atomicAdd(&g_hist[2 * 65536 + (__float_as_uint(v) >> 16)], 1u);
    }
    if (tid < 16) {  // w=8: 1x16
        float s = 0.0f;
        for (int a = 0; a < 8; a++)
            for (int b = 0; b < 8; b++)
                s += ent_s[a * 128 + tid * 8 + b];
        float v = s * (1.0f / 64.0f);
        g_p3[blk * 16 + tid] = v;
        atomicAdd(&g_hist[3 * 65536 + (__float_as_uint(v) >> 16)], 1u);
    }
}

// ---------------- grid-parallel two-level radix select ----------------
__device__ __forceinline__ const float* sel_elem(int g, int& s, int& i) {
    if (g < 131072)      { s = 0; i = g;          return g_ent; }
    else if (g < 163840) { s = 1; i = g - 131072; return g_p1;  }
    else if (g < 172032) { s = 2; i = g - 163840; return g_p2;  }
    else                 { s = 3; i = g - 172032; return g_p3;  }
}

__global__ __launch_bounds__(256)
void hist2_k()
{
    int g = blockIdx.x * 256 + threadIdx.x;
    int s, i;
    const float* d = sel_elem(g, s, i);
    unsigned u = __float_as_uint(d[i]);
    if ((u >> 16) == g_pref[s])
        atomicAdd(&g_hist[s * 65536 + (u & 0xFFFFu)], 1u);
}

// One block per scale. LEVEL=0: writes g_pref/g_krem. LEVEL=1: writes g_T.
template<int LEVEL>
__global__ __launch_bounds__(1024)
void scan_k()
{
    int s = blockIdx.x;
    int t = threadIdx.x;

    if (LEVEL == 1 && s == 4) {   // variance finalize (128 block partials)
        __shared__ float rs[128], rq[128];
        if (t < 128) { rs[t] = g_part[t]; rq[t] = g_part[512 + t]; }
        __syncthreads();
        for (int st = 64; st > 0; st >>= 1) {
            if (t < st) { rs[t] += rs[t + st]; rq[t] += rq[t + st]; }
            __syncthreads();
        }
        if (t == 0) { g_stats[0] = rs[0]; g_stats[1] = rq[0]; }
        return;
    }

    unsigned* h = g_hist + s * 65536;
    unsigned K = (LEVEL == 0) ? (unsigned)c_K[s] : g_krem[s];

    unsigned p = 0;
#pragma unroll 8
    for (int j = 0; j < 64; j++) p += h[t * 64 + j];

    __shared__ unsigned ssA[1024], ssB[1024];
    ssA[t] = p;
    __syncthreads();
    unsigned* src = ssA; unsigned* dst = ssB;
#pragma unroll
    for (int off = 1; off < 1024; off <<= 1) {
        unsigned v = src[t] + ((t + off < 1024) ? src[t + off] : 0u);
        __syncthreads();
        dst[t] = v;
        __syncthreads();
        unsigned* tmp = src; src = dst; dst = tmp;
    }
    unsigned incl = src[t];
    unsigned above = incl - p;

    if (incl >= K && above < K) {
        unsigned cum = above;
        for (int j = 63; j >= 0; j--) {
            unsigned c = h[t * 64 + j];
            if (cum + c >= K) {
                unsigned bin = (unsigned)(t * 64 + j);
                if (LEVEL == 0) { g_pref[s] = bin; g_krem[s] = K - cum; }
                else            g_T[s] = __uint_as_float((g_pref[s] << 16) | bin);
                break;
            }
            cum += c;
        }
    }
    __syncthreads();
#pragma unroll 8
    for (int j = 0; j < 64; j++) h[t * 64 + j] = 0u;
}

// ---------------- final update ----------------
__global__ __launch_bounds__(256)
void update_k(const float* __restrict__ z, const float* __restrict__ y,
              const float* __restrict__ msk, float* __restrict__ out,
              float base_a, float base_b, float h_lam)
{
    int i = blockIdx.x * 256 + threadIdx.x;
    int l = i / C_, c = i % C_;

    int sfound = -1; float ent = 0.0f;
    float v0 = g_ent[i];
    if (v0 >= g_T[0]) { sfound = 0; ent = v0; }
    else {
        float v1 = g_p1[(l >> 1) * (C_ / 2) + (c >> 1)];
        if (v1 >= g_T[1]) { sfound = 1; ent = v1; }
        else {
            float v2 = g_p2[(l >> 2) * (C_ / 4) + (c >> 2)];
            if (v2 >= g_T[2]) { sfound = 2; ent = v2; }
            else {
                float v3 = g_p3[(l >> 3) * (C_ / 8) + (c >> 3)];
                if (v3 >= g_T[3]) { sfound = 3; ent = v3; }
            }
        }
    }

    if (sfound < 0) {
#pragma unroll
        for (int b = 0; b < B_; b++) {
            size_t o = (size_t)b * LC_ + i;
            out[o] = z[o];
        }
        return;
    }

    const float invN = 1.0f / (float)(B_ * LC_);
    float mean = g_stats[0] * invN;
    float var  = g_stats[1] * invN - mean * mean;
    float inv_d = 1.0f / (var + 1e-8f);

    float om1 = (ent > 0.1f ? 1.0f : 0.0f) + (ent > 0.5f ? 1.0f : 0.0f);
    float corr = 1.0f + om1 * 0.5f * h_lam
               + om1 * (om1 - 1.0f) * (1.0f / 6.0f) * h_lam * h_lam;
    float gs = 2.0f * ent / (ent + 1.0f);
    float bb = base_b * corr;

#pragma unroll
    for (int b = 0; b < B_; b++) {
        size_t o = (size_t)b * LC_ + i;
        float zv = z[o];
        float gd = -(zv - y[o]) * msk[o] * inv_d;
        out[o] = base_a * zv - bb * g_eps[o] + gs * gd;
    }
}

// ---------------- host driver ----------------
extern "C" void kernel_launch(void* const* d_in, const int* in_sizes, int n_in,
                              void* d_out, int out_size)
{
    const float* y   = (const float*)d_in[0];
    const float* msk = (const float*)d_in[1];
    const float* z0  = (const float*)d_in[2];
    const float* W1  = (const float*)d_in[3];
    const float* b1  = (const float*)d_in[4];
    const float* W2  = (const float*)d_in[5];
    const float* b2  = (const float*)d_in[6];
    const float* tw  = (const float*)d_in[7];

    static float ac[1000];
    {
        float run = 1.0f;
        for (int i = 0; i < 1000; i++) {
            float beta = 1e-4f + (0.02f - 1e-4f) * ((float)i / 999.0f);
            run *= (1.0f - beta);
            ac[i] = run;
        }
    }
    auto alpha_at = [&](int i) { return sqrtf(ac[i]); };
    auto sigma_at = [&](int i) { return sqrtf(1.0f - ac[i]); };
    auto lam_at   = [&](int i) { return logf(alpha_at(i)) - logf(sigma_at(i)); };

    float *p_h, *p_eps, *p_za, *p_zb;
    cudaGetSymbolAddress((void**)&p_h,   g_h);
    cudaGetSymbolAddress((void**)&p_eps, g_eps);
    cudaGetSymbolAddress((void**)&p_za,  g_za);
    cudaGetSymbolAddress((void**)&p_zb,  g_zb);
    __nv_bfloat16 *b1t0, *b1t1, *b1t2, *b2t0, *b2t1, *b2t2;
    cudaGetSymbolAddress((void**)&b1t0, g_b1t0);
    cudaGetSymbolAddress((void**)&b1t1, g_b1t1);
    cudaGetSymbolAddress((void**)&b1t2, g_b1t2);
    cudaGetSymbolAddress((void**)&b2t0, g_b2t0);
    cudaGetSymbolAddress((void**)&b2t1, g_b2t1);
    cudaGetSymbolAddress((void**)&b2t2, g_b2t2);

    cudaFuncSetAttribute(gemm_mma<128, true >, cudaFuncAttributeMaxDynamicSharedMemorySize, SMEMB);
    cudaFuncSetAttribute(gemm_mma<512, false>, cudaFuncAttributeMaxDynamicSharedMemorySize, SMEMB);

    const float* zin[4]  = { z0,  p_za, p_zb, p_za };
    float*       zout[4] = { p_za, p_zb, p_za, (float*)d_out };

    prep_k<<<512, 256>>>(W1, W2);

    const int step = 1000 / 4;
    dim3 grid1(H_ / 128, M_ / 128);   // (4, 128)
    dim3 grid2(C_ / 128, M_ / 128);   // (1, 128)

    for (int si = 0; si < 4; si++) {
        int k  = 999 - si * step;
        int kp = k - step; if (kp < 0) kp = 0;
        float t_feat = (float)k / 1000.0f;
        float h_lam  = lam_at(kp) - lam_at(k);
        float base_a = alpha_at(kp) / alpha_at(k);
        float base_b = sigma_at(kp) * (expf(h_lam) - 1.0f);

        gemm_mma<128, true ><<<grid1, 256, SMEMB>>>(zin[si], b1t0, b1t1, b1t2,
                                                    b1, tw, t_feat, p_h, H_);
        gemm_mma<512, false><<<grid2, 256, SMEMB>>>(p_h, b2t0, b2t1, b2t2,
                                                    b2, b2, 0.0f, p_eps, C_);
        fstats_k<<<128, 1024>>>(zin[si], y, msk);
        scan_k<0><<<4, 1024>>>();
        hist2_k <<<680, 256>>>();
        scan_k<1><<<5, 1024>>>();
        update_k<<<LC_ / 256, 256>>>(zin[si], y, msk, zout[si], base_a, base_b, h_lam);
    }
}

// round 11
// speedup vs baseline: 1.9956x; 1.0301x over previous
#include <cuda_runtime.h>
#include <cuda_bf16.h>
#include <math.h>
#include <stdint.h>

#define B_  16
#define L_  1024
#define C_  128
#define H_  512
#define LC_ (L_*C_)      // 131072
#define M_  (B_*L_)      // 16384

// ---------------- device scratch ----------------
__device__ float g_h  [M_*H_];        // 32 MB hidden activations (fp32)
__device__ float g_eps[M_*C_];
__device__ float g_za [M_*C_];
__device__ float g_zb [M_*C_];
__device__ float g_ent[LC_];
__device__ float g_p1[(L_/2)*(C_/2)];   // 32768
__device__ float g_p2[(L_/4)*(C_/4)];   // 8192
__device__ float g_p3[(L_/8)*(C_/8)];   // 2048
__device__ float g_part[1024];          // 128 used per half
__device__ float g_T[4];
__device__ float g_stats[2];
__device__ unsigned g_hist[4 * 65536];  // zero-invariant across replays
__device__ unsigned g_pref[4];
__device__ unsigned g_krem[4];
// weight splits (3-term), transposed [N,K] row-major (K contiguous)
__device__ __nv_bfloat16 g_b1t0[H_*C_], g_b1t1[H_*C_], g_b1t2[H_*C_]; // [512,128]
__device__ __nv_bfloat16 g_b2t0[C_*H_], g_b2t1[C_*H_], g_b2t2[C_*H_]; // [128,512]

__constant__ int c_K[4] = { 26214, 6553, 1638, 409 };   // int(0.2 * pooled.size)

// ---------------- helpers ----------------
__device__ __forceinline__ uint32_t smem_u32(const void* p) {
    uint32_t a;
    asm("{ .reg .u64 t; cvta.to.shared.u64 t, %1; cvt.u32.u64 %0, t; }" : "=r"(a) : "l"(p));
    return a;
}
__device__ __forceinline__ void cp_async16(uint32_t s, const void* g) {
    asm volatile("cp.async.cg.shared.global [%0], [%1], 16;" :: "r"(s), "l"(g) : "memory");
}
#define STS64v(addr, r0, r1) \
    asm volatile("st.shared.v2.b32 [%0], {%1,%2};" :: "r"(addr), "r"(r0), "r"(r1) : "memory")
__device__ __forceinline__ void ldsm_x4(uint32_t* r, uint32_t addr) {
    asm volatile("ldmatrix.sync.aligned.m8n8.x4.shared.b16 {%0,%1,%2,%3}, [%4];"
                 : "=r"(r[0]), "=r"(r[1]), "=r"(r[2]), "=r"(r[3]) : "r"(addr));
}
__device__ __forceinline__ void mma16816(float* d, const uint32_t* a, const uint32_t* b) {
    asm volatile(
        "mma.sync.aligned.m16n8k16.row.col.f32.bf16.bf16.f32 "
        "{%0,%1,%2,%3}, {%4,%5,%6,%7}, {%8,%9}, {%0,%1,%2,%3};"
        : "+f"(d[0]), "+f"(d[1]), "+f"(d[2]), "+f"(d[3])
        : "r"(a[0]), "r"(a[1]), "r"(a[2]), "r"(a[3]), "r"(b[0]), "r"(b[1]));
}
// gelu(x) = x * sigmoid(2u); exactly 2 MUFU, no branch. (validated R10)
__device__ __forceinline__ float gelu_f(float x) {
    float x2 = x * x;
    float u  = 0.7978845608028654f * x + 0.035677408136300125f * x * x2;
    float e, r;
    asm("ex2.approx.f32 %0, %1;" : "=f"(e) : "f"(-2.8853900817779268f * u));
    asm("rcp.approx.f32 %0, %1;" : "=f"(r) : "f"(1.0f + e));
    return x * r;
}
__device__ __forceinline__ void split3(float x, unsigned short& h0, unsigned short& h1, unsigned short& h2) {
    __nv_bfloat16 b0 = __float2bfloat16_rn(x);
    float r1 = x - __bfloat162float(b0);
    __nv_bfloat16 b1 = __float2bfloat16_rn(r1);
    float r2 = r1 - __bfloat162float(b1);
    __nv_bfloat16 b2 = __float2bfloat16_rn(r2);
    h0 = __bfloat16_as_ushort(b0);
    h1 = __bfloat16_as_ushort(b1);
    h2 = __bfloat16_as_ushort(b2);
}

// ---------------- weight prep: transpose + 3-way split ------------------
__global__ __launch_bounds__(256) void prep_k(const float* __restrict__ W1, const float* __restrict__ W2)
{
    int t = blockIdx.x * 256 + threadIdx.x;   // 131072 total
    float x; int idx;
    __nv_bfloat16 *d0, *d1, *d2;
    if (t < H_ * C_) {                        // B1t [512,128] from W1[128,512]
        idx = t; int n = idx >> 7, k = idx & 127;
        x = W1[k * H_ + n];
        d0 = g_b1t0; d1 = g_b1t1; d2 = g_b1t2;
    } else {                                  // B2t [128,512] from W2[512,128]
        idx = t - H_ * C_; int n = idx >> 9, k = idx & 511;
        x = W2[k * C_ + n];
        d0 = g_b2t0; d1 = g_b2t1; d2 = g_b2t2;
    }
    unsigned short h0, h1, h2;
    split3(x, h0, h1, h2);
    d0[idx] = __ushort_as_bfloat16(h0);
    d1[idx] = __ushort_as_bfloat16(h1);
    d2[idx] = __ushort_as_bfloat16(h2);
}

static constexpr int TERMB = 10240;   // 128 rows x 80B (64B data + 16B pad)

// ================= GEMM1: one-wave, A-resident ==========================
// h[M,512] = gelu(z[M,128] @ W1 + b1 + t*tw). grid=128 (m-tiles), 256 thr.
// A (128x128 fp32) split into smem ONCE (3 terms x 4 k-chunks = 120KB),
// then 4 n-tiles x 4 k-tiles with double-buffered B (60KB). One wave.
static constexpr int A1BYTES = 12 * TERMB;           // 122880
static constexpr int SMEMB1  = A1BYTES + 6 * TERMB;  // 184320

__global__ __launch_bounds__(256, 1)
void gemm1_k(const float* __restrict__ A,
             const __nv_bfloat16* __restrict__ Bt0, const __nv_bfloat16* __restrict__ Bt1,
             const __nv_bfloat16* __restrict__ Bt2,
             const float* __restrict__ bias, const float* __restrict__ tw, float t_feat,
             float* __restrict__ out)
{
    extern __shared__ char smem[];
    const uint32_t sb = smem_u32(smem);
    const int tid = threadIdx.x, lane = tid & 31, wid = tid >> 5;
    const int m0 = blockIdx.x * 128;
    const int wm = (wid >> 2) * 64, wn = (wid & 3) * 32;

    auto cpB = [&](int n, int kt, int buf) {
        uint32_t base = sb + A1BYTES + buf * (3 * TERMB);
#pragma unroll
        for (int i = 0; i < 6; i++) {
            int rem = (i & 1) * 256 + tid;
            int row = rem >> 2, ch = rem & 3;
            const __nv_bfloat16* src = (i < 2) ? Bt0 : ((i < 4) ? Bt1 : Bt2);
            cp_async16(base + (i >> 1) * TERMB + row * 80 + ch * 16,
                       src + (size_t)(n * 128 + row) * C_ + kt * 32 + ch * 8);
        }
        asm volatile("cp.async.commit_group;" ::: "memory");
    };

    // kick off first B tile, then split A while it flies
    cpB(0, 0, 0);

    // A prologue: load fp32, split3, store all 4 k-chunks (A[t][kt] layout)
#pragma unroll
    for (int c = 0; c < 4; c++) {
        float4 aR[4];
#pragma unroll
        for (int i = 0; i < 4; i++) {
            int f = tid + i * 256;
            aR[i] = *(const float4*)(A + (size_t)(m0 + (f >> 3)) * C_ + c * 32 + (f & 7) * 4);
        }
#pragma unroll
        for (int i = 0; i < 4; i++) {
            int f = tid + i * 256;
            float x[4] = { aR[i].x, aR[i].y, aR[i].z, aR[i].w };
            unsigned short s0[4], s1[4], s2[4];
#pragma unroll
            for (int j = 0; j < 4; j++) split3(x[j], s0[j], s1[j], s2[j]);
            uint32_t addr = sb + c * TERMB + (f >> 3) * 80 + (f & 7) * 8;
            STS64v(addr,                 (uint32_t)s0[0] | ((uint32_t)s0[1] << 16),
                                         (uint32_t)s0[2] | ((uint32_t)s0[3] << 16));
            STS64v(addr + 4 * TERMB,     (uint32_t)s1[0] | ((uint32_t)s1[1] << 16),
                                         (uint32_t)s1[2] | ((uint32_t)s1[3] << 16));
            STS64v(addr + 8 * TERMB,     (uint32_t)s2[0] | ((uint32_t)s2[1] << 16),
                                         (uint32_t)s2[2] | ((uint32_t)s2[3] << 16));
        }
    }

    const int PA[6] = { 0, 0, 1, 1, 0, 2 };
    const int PB[6] = { 0, 1, 0, 1, 2, 0 };
    int buf = 0;

#pragma unroll 1
    for (int n = 0; n < 4; n++) {
        float acc[4][4][4];
#pragma unroll
        for (int a = 0; a < 4; a++)
#pragma unroll
            for (int b = 0; b < 4; b++)
#pragma unroll
                for (int c = 0; c < 4; c++) acc[a][b][c] = 0.0f;

#pragma unroll 1
        for (int kt = 0; kt < 4; kt++) {
            int idx = n * 4 + kt;
            if (idx + 1 < 16) {
                int nn = (idx + 1) >> 2, nk = (idx + 1) & 3;
                cpB(nn, nk, buf ^ 1);
                asm volatile("cp.async.wait_group 1;" ::: "memory");
            } else {
                asm volatile("cp.async.wait_group 0;" ::: "memory");
            }
            __syncthreads();

            uint32_t baseB = sb + A1BYTES + buf * (3 * TERMB);
#pragma unroll
            for (int kk = 0; kk < 2; kk++) {
                uint32_t aF[3][4][4];
                uint32_t bF[3][4][2];
#pragma unroll
                for (int t = 0; t < 3; t++) {
#pragma unroll
                    for (int mi = 0; mi < 4; mi++) {
                        uint32_t addr = sb + (t * 4 + kt) * TERMB
                            + (wm + mi * 16 + (lane & 15)) * 80
                            + kk * 32 + (lane >> 4) * 16;
                        ldsm_x4(aF[t][mi], addr);
                    }
#pragma unroll
                    for (int nt = 0; nt < 2; nt++) {
                        int row = wn + nt * 16 + ((lane >> 4) & 1) * 8 + (lane & 7);
                        uint32_t addr = baseB + t * TERMB
                            + row * 80 + kk * 32 + ((lane >> 3) & 1) * 16;
                        uint32_t r[4];
                        ldsm_x4(r, addr);
                        bF[t][nt * 2][0]     = r[0]; bF[t][nt * 2][1]     = r[1];
                        bF[t][nt * 2 + 1][0] = r[2]; bF[t][nt * 2 + 1][1] = r[3];
                    }
                }
#pragma unroll
                for (int p = 0; p < 6; p++) {
#pragma unroll
                    for (int mi = 0; mi < 4; mi++)
#pragma unroll
                        for (int ni = 0; ni < 4; ni++)
                            mma16816(acc[mi][ni], aF[PA[p]][mi], bF[PB[p]][ni]);
                }
            }
            __syncthreads();
            buf ^= 1;
        }

        // epilogue for this n-tile: bias + time + gelu, fp32 stores into h
        int n0 = n * 128;
#pragma unroll
        for (int mi = 0; mi < 4; mi++) {
#pragma unroll
            for (int ni = 0; ni < 4; ni++) {
                int r0 = m0 + wm + mi * 16 + (lane >> 2);
                int r1 = r0 + 8;
                int c  = n0 + wn + ni * 8 + (lane & 3) * 2;
                float bz0 = __ldg(bias + c)     + t_feat * __ldg(tw + c);
                float bz1 = __ldg(bias + c + 1) + t_feat * __ldg(tw + c + 1);
                float v00 = gelu_f(acc[mi][ni][0] + bz0);
                float v01 = gelu_f(acc[mi][ni][1] + bz1);
                float v10 = gelu_f(acc[mi][ni][2] + bz0);
                float v11 = gelu_f(acc[mi][ni][3] + bz1);
                *(float2*)(out + (size_t)r0 * H_ + c) = make_float2(v00, v01);
                *(float2*)(out + (size_t)r1 * H_ + c) = make_float2(v10, v11);
            }
        }
    }
}

// ================= GEMM2: K=512 streaming (proven config) ===============
static constexpr int ABYTES = 2 * 3 * TERMB;   // A bf16 region (2 bufs x 3 terms)
static constexpr int SMEMB2 = 2 * ABYTES;      // 122880

__global__ __launch_bounds__(256, 1)
void gemm2_k(const float* __restrict__ A,
             const __nv_bfloat16* __restrict__ Bt0, const __nv_bfloat16* __restrict__ Bt1,
             const __nv_bfloat16* __restrict__ Bt2,
             const float* __restrict__ bias, float* __restrict__ out)
{
    extern __shared__ char smem[];
    const uint32_t sb = smem_u32(smem);
    const int tid = threadIdx.x, lane = tid & 31, wid = tid >> 5;
    const int m0 = blockIdx.y * 128, n0 = blockIdx.x * 128;
    const int wm = (wid >> 2) * 64, wn = (wid & 3) * 32;
    const int KTOT = H_;

    float acc[4][4][4];
#pragma unroll
    for (int a = 0; a < 4; a++)
#pragma unroll
        for (int b = 0; b < 4; b++)
#pragma unroll
            for (int c = 0; c < 4; c++) acc[a][b][c] = 0.0f;

    float4 aR[4];
    auto ldgA = [&](int kt) {
#pragma unroll
        for (int i = 0; i < 4; i++) {
            int f = tid + i * 256;
            aR[i] = *(const float4*)(A + (size_t)(m0 + (f >> 3)) * KTOT + kt * 32 + (f & 7) * 4);
        }
    };
    auto stsA = [&](int buf) {
        uint32_t base = sb + buf * (3 * TERMB);
#pragma unroll
        for (int i = 0; i < 4; i++) {
            int f = tid + i * 256;
            float x[4] = { aR[i].x, aR[i].y, aR[i].z, aR[i].w };
            unsigned short s0[4], s1[4], s2[4];
#pragma unroll
            for (int j = 0; j < 4; j++) split3(x[j], s0[j], s1[j], s2[j]);
            uint32_t addr = base + (f >> 3) * 80 + (f & 7) * 8;
            STS64v(addr,             (uint32_t)s0[0] | ((uint32_t)s0[1] << 16),
                                     (uint32_t)s0[2] | ((uint32_t)s0[3] << 16));
            STS64v(addr + TERMB,     (uint32_t)s1[0] | ((uint32_t)s1[1] << 16),
                                     (uint32_t)s1[2] | ((uint32_t)s1[3] << 16));
            STS64v(addr + 2 * TERMB, (uint32_t)s2[0] | ((uint32_t)s2[1] << 16),
                                     (uint32_t)s2[2] | ((uint32_t)s2[3] << 16));
        }
    };
    auto cpB = [&](int kt, int buf) {
        uint32_t base = sb + ABYTES + buf * (3 * TERMB);
#pragma unroll
        for (int i = 0; i < 6; i++) {
            int rem = (i & 1) * 256 + tid;
            int row = rem >> 2, ch = rem & 3;
            const __nv_bfloat16* src = (i < 2) ? Bt0 : ((i < 4) ? Bt1 : Bt2);
            cp_async16(base + (i >> 1) * TERMB + row * 80 + ch * 16,
                       src + (size_t)(n0 + row) * KTOT + kt * 32 + ch * 8);
        }
        asm volatile("cp.async.commit_group;" ::: "memory");
    };

    const int NKT = KTOT / 32;
    ldgA(0);
    cpB(0, 0);
    int buf = 0;

    const int PA[6] = { 0, 0, 1, 1, 0, 2 };
    const int PB[6] = { 0, 1, 0, 1, 2, 0 };

#pragma unroll 1
    for (int kt = 0; kt < NKT; kt++) {
        stsA(buf);
        if (kt + 1 < NKT) {
            cpB(kt + 1, buf ^ 1);
            ldgA(kt + 1);
            asm volatile("cp.async.wait_group 1;" ::: "memory");
        } else {
            asm volatile("cp.async.wait_group 0;" ::: "memory");
        }
        __syncthreads();

        uint32_t baseA = sb + buf * (3 * TERMB);
        uint32_t baseB = sb + ABYTES + buf * (3 * TERMB);
#pragma unroll
        for (int kk = 0; kk < 2; kk++) {
            uint32_t aF[3][4][4];
            uint32_t bF[3][4][2];
#pragma unroll
            for (int t = 0; t < 3; t++) {
#pragma unroll
                for (int mi = 0; mi < 4; mi++) {
                    uint32_t addr = baseA + t * TERMB
                        + (wm + mi * 16 + (lane & 15)) * 80
                        + kk * 32 + (lane >> 4) * 16;
                    ldsm_x4(aF[t][mi], addr);
                }
#pragma unroll
                for (int nt = 0; nt < 2; nt++) {
                    int row = wn + nt * 16 + ((lane >> 4) & 1) * 8 + (lane & 7);
                    uint32_t addr = baseB + t * TERMB
                        + row * 80 + kk * 32 + ((lane >> 3) & 1) * 16;
                    uint32_t r[4];
                    ldsm_x4(r, addr);
                    bF[t][nt * 2][0]     = r[0]; bF[t][nt * 2][1]     = r[1];
                    bF[t][nt * 2 + 1][0] = r[2]; bF[t][nt * 2 + 1][1] = r[3];
                }
            }
#pragma unroll
            for (int p = 0; p < 6; p++) {
#pragma unroll
                for (int mi = 0; mi < 4; mi++)
#pragma unroll
                    for (int ni = 0; ni < 4; ni++)
                        mma16816(acc[mi][ni], aF[PA[p]][mi], bF[PB[p]][ni]);
            }
        }
        __syncthreads();
        buf ^= 1;
    }

#pragma unroll
    for (int mi = 0; mi < 4; mi++) {
#pragma unroll
        for (int ni = 0; ni < 4; ni++) {
            int r0 = m0 + wm + mi * 16 + (lane >> 2);
            int r1 = r0 + 8;
            int c  = n0 + wn + ni * 8 + (lane & 3) * 2;
            float bz0 = __ldg(bias + c);
            float bz1 = __ldg(bias + c + 1);
            *(float2*)(out + (size_t)r0 * C_ + c) = make_float2(acc[mi][ni][0] + bz0, acc[mi][ni][1] + bz1);
            *(float2*)(out + (size_t)r1 * C_ + c) = make_float2(acc[mi][ni][2] + bz0, acc[mi][ni][3] + bz1);
        }
    }
}

// ---------------- fused: entropy + obs_err partials + pooling + hist16 ---
__global__ __launch_bounds__(1024)
void fstats_k(const float* __restrict__ z, const float* __restrict__ y,
              const float* __restrict__ msk)
{
    int blk = blockIdx.x;
    int tid = threadIdx.x;
    __shared__ float ent_s[1024];
    __shared__ float rs[1024], rq[1024];

    int p = blk * 1024 + tid;
    float sa = 0.0f;
#pragma unroll
    for (int b = 0; b < B_; b++) sa += fabsf(g_eps[(size_t)b * LC_ + p]);
    float e = sa * (1.0f / B_);
    g_ent[p] = e;
    ent_s[tid] = e;
    atomicAdd(&g_hist[__float_as_uint(e) >> 16], 1u);

    float ps = 0.0f, pq = 0.0f;
#pragma unroll
    for (int b = 0; b < B_; b++) {
        size_t o = (size_t)b * LC_ + p;
        float t = (z[o] - y[o]) * msk[o];
        ps += t; pq += t * t;
    }
    rs[tid] = ps; rq[tid] = pq;
    __syncthreads();
    for (int st = 512; st > 0; st >>= 1) {
        if (tid < st) { rs[tid] += rs[tid + st]; rq[tid] += rq[tid + st]; }
        __syncthreads();
    }
    if (tid == 0) { g_part[blk] = rs[0]; g_part[512 + blk] = rq[0]; }

    if (tid < 256) {   // w=2: 4x64
        int pr = tid >> 6, pc = tid & 63;
        float s = 0.0f;
        for (int a = 0; a < 2; a++)
            for (int b = 0; b < 2; b++)
                s += ent_s[(pr * 2 + a) * 128 + pc * 2 + b];
        float v = s * 0.25f;
        g_p1[(blk * 4 + pr) * 64 + pc] = v;
        atomicAdd(&g_hist[65536 + (__float_as_uint(v) >> 16)], 1u);
    }
    if (tid < 64) {  // w=4: 2x32
        int pr = tid >> 5, pc = tid & 31;
        float s = 0.0f;
        for (int a = 0; a < 4; a++)
            for (int b = 0; b < 4; b++)
                s += ent_s[(pr * 4 + a) * 128 + pc * 4 + b];
        float v = s * (1.0f / 16.0f);
        g_p2[(blk * 2 + pr) * 32 + pc] = v;
        atomicAdd(&g_hist[2 * 65536 + (__float_as_uint(v) >> 16)], 1u);
    }
    if (tid < 16) {  // w=8: 1x16
        float s = 0.0f;
        for (int a = 0; a < 8; a++)
            for (int b = 0; b < 8; b++)
                s += ent_s[a * 128 + tid * 8 + b];
        float v = s * (1.0f / 64.0f);
        g_p3[blk * 16 + tid] = v;
        atomicAdd(&g_hist[3 * 65536 + (__float_as_uint(v) >> 16)], 1u);
    }
}

// ---------------- grid-parallel two-level radix select ----------------
__device__ __forceinline__ const float* sel_elem(int g, int& s, int& i) {
    if (g < 131072)      { s = 0; i = g;          return g_ent; }
    else if (g < 163840) { s = 1; i = g - 131072; return g_p1;  }
    else if (g < 172032) { s = 2; i = g - 163840; return g_p2;  }
    else                 { s = 3; i = g - 172032; return g_p3;  }
}

__global__ __launch_bounds__(256)
void hist2_k()
{
    int g = blockIdx.x * 256 + threadIdx.x;
    int s, i;
    const float* d = sel_elem(g, s, i);
    unsigned u = __float_as_uint(d[i]);
    if ((u >> 16) == g_pref[s])
        atomicAdd(&g_hist[s * 65536 + (u & 0xFFFFu)], 1u);
}

template<int LEVEL>
__global__ __launch_bounds__(1024)
void scan_k()
{
    int s = blockIdx.x;
    int t = threadIdx.x;

    if (LEVEL == 1 && s == 4) {   // variance finalize (128 block partials)
        __shared__ float rs[128], rq[128];
        if (t < 128) { rs[t] = g_part[t]; rq[t] = g_part[512 + t]; }
        __syncthreads();
        for (int st = 64; st > 0; st >>= 1) {
            if (t < st) { rs[t] += rs[t + st]; rq[t] += rq[t + st]; }
            __syncthreads();
        }
        if (t == 0) { g_stats[0] = rs[0]; g_stats[1] = rq[0]; }
        return;
    }

    unsigned* h = g_hist + s * 65536;
    unsigned K = (LEVEL == 0) ? (unsigned)c_K[s] : g_krem[s];

    unsigned p = 0;
#pragma unroll 8
    for (int j = 0; j < 64; j++) p += h[t * 64 + j];

    __shared__ unsigned ssA[1024], ssB[1024];
    ssA[t] = p;
    __syncthreads();
    unsigned* src = ssA; unsigned* dst = ssB;
#pragma unroll
    for (int off = 1; off < 1024; off <<= 1) {
        unsigned v = src[t] + ((t + off < 1024) ? src[t + off] : 0u);
        __syncthreads();
        dst[t] = v;
        __syncthreads();
        unsigned* tmp = src; src = dst; dst = tmp;
    }
    unsigned incl = src[t];
    unsigned above = incl - p;

    if (incl >= K && above < K) {
        unsigned cum = above;
        for (int j = 63; j >= 0; j--) {
            unsigned c = h[t * 64 + j];
            if (cum + c >= K) {
                unsigned bin = (unsigned)(t * 64 + j);
                if (LEVEL == 0) { g_pref[s] = bin; g_krem[s] = K - cum; }
                else            g_T[s] = __uint_as_float((g_pref[s] << 16) | bin);
                break;
            }
            cum += c;
        }
    }
    __syncthreads();
#pragma unroll 8
    for (int j = 0; j < 64; j++) h[t * 64 + j] = 0u;
}

// ---------------- final update ----------------
__global__ __launch_bounds__(256)
void update_k(const float* __restrict__ z, const float* __restrict__ y,
              const float* __restrict__ msk, float* __restrict__ out,
              float base_a, float base_b, float h_lam)
{
    int i = blockIdx.x * 256 + threadIdx.x;
    int l = i / C_, c = i % C_;

    int sfound = -1; float ent = 0.0f;
    float v0 = g_ent[i];
    if (v0 >= g_T[0]) { sfound = 0; ent = v0; }
    else {
        float v1 = g_p1[(l >> 1) * (C_ / 2) + (c >> 1)];
        if (v1 >= g_T[1]) { sfound = 1; ent = v1; }
        else {
            float v2 = g_p2[(l >> 2) * (C_ / 4) + (c >> 2)];
            if (v2 >= g_T[2]) { sfound = 2; ent = v2; }
            else {
                float v3 = g_p3[(l >> 3) * (C_ / 8) + (c >> 3)];
                if (v3 >= g_T[3]) { sfound = 3; ent = v3; }
            }
        }
    }

    if (sfound < 0) {
#pragma unroll
        for (int b = 0; b < B_; b++) {
            size_t o = (size_t)b * LC_ + i;
            out[o] = z[o];
        }
        return;
    }

    const float invN = 1.0f / (float)(B_ * LC_);
    float mean = g_stats[0] * invN;
    float var  = g_stats[1] * invN - mean * mean;
    float inv_d = 1.0f / (var + 1e-8f);

    float om1 = (ent > 0.1f ? 1.0f : 0.0f) + (ent > 0.5f ? 1.0f : 0.0f);
    float corr = 1.0f + om1 * 0.5f * h_lam
               + om1 * (om1 - 1.0f) * (1.0f / 6.0f) * h_lam * h_lam;
    float gs = 2.0f * ent / (ent + 1.0f);
    float bb = base_b * corr;

#pragma unroll
    for (int b = 0; b < B_; b++) {
        size_t o = (size_t)b * LC_ + i;
        float zv = z[o];
        float gd = -(zv - y[o]) * msk[o] * inv_d;
        out[o] = base_a * zv - bb * g_eps[o] + gs * gd;
    }
}

// ---------------- host driver ----------------
extern "C" void kernel_launch(void* const* d_in, const int* in_sizes, int n_in,
                              void* d_out, int out_size)
{
    const float* y   = (const float*)d_in[0];
    const float* msk = (const float*)d_in[1];
    const float* z0  = (const float*)d_in[2];
    const float* W1  = (const float*)d_in[3];
    const float* b1  = (const float*)d_in[4];
    const float* W2  = (const float*)d_in[5];
    const float* b2  = (const float*)d_in[6];
    const float* tw  = (const float*)d_in[7];

    static float ac[1000];
    {
        float run = 1.0f;
        for (int i = 0; i < 1000; i++) {
            float beta = 1e-4f + (0.02f - 1e-4f) * ((float)i / 999.0f);
            run *= (1.0f - beta);
            ac[i] = run;
        }
    }
    auto alpha_at = [&](int i) { return sqrtf(ac[i]); };
    auto sigma_at = [&](int i) { return sqrtf(1.0f - ac[i]); };
    auto lam_at   = [&](int i) { return logf(alpha_at(i)) - logf(sigma_at(i)); };

    float *p_h, *p_eps, *p_za, *p_zb;
    cudaGetSymbolAddress((void**)&p_h,   g_h);
    cudaGetSymbolAddress((void**)&p_eps, g_eps);
    cudaGetSymbolAddress((void**)&p_za,  g_za);
    cudaGetSymbolAddress((void**)&p_zb,  g_zb);
    __nv_bfloat16 *b1t0, *b1t1, *b1t2, *b2t0, *b2t1, *b2t2;
    cudaGetSymbolAddress((void**)&b1t0, g_b1t0);
    cudaGetSymbolAddress((void**)&b1t1, g_b1t1);
    cudaGetSymbolAddress((void**)&b1t2, g_b1t2);
    cudaGetSymbolAddress((void**)&b2t0, g_b2t0);
    cudaGetSymbolAddress((void**)&b2t1, g_b2t1);
    cudaGetSymbolAddress((void**)&b2t2, g_b2t2);

    cudaFuncSetAttribute(gemm1_k, cudaFuncAttributeMaxDynamicSharedMemorySize, SMEMB1);
    cudaFuncSetAttribute(gemm2_k, cudaFuncAttributeMaxDynamicSharedMemorySize, SMEMB2);

    const float* zin[4]  = { z0,  p_za, p_zb, p_za };
    float*       zout[4] = { p_za, p_zb, p_za, (float*)d_out };

    prep_k<<<512, 256>>>(W1, W2);

    const int step = 1000 / 4;
    dim3 grid2(C_ / 128, M_ / 128);   // (1, 128)

    for (int si = 0; si < 4; si++) {
        int k  = 999 - si * step;
        int kp = k - step; if (kp < 0) kp = 0;
        float t_feat = (float)k / 1000.0f;
        float h_lam  = lam_at(kp) - lam_at(k);
        float base_a = alpha_at(kp) / alpha_at(k);
        float base_b = sigma_at(kp) * (expf(h_lam) - 1.0f);

        gemm1_k<<<M_ / 128, 256, SMEMB1>>>(zin[si], b1t0, b1t1, b1t2, b1, tw, t_feat, p_h);
        gemm2_k<<<grid2, 256, SMEMB2>>>(p_h, b2t0, b2t1, b2t2, b2, p_eps);
        fstats_k<<<128, 1024>>>(zin[si], y, msk);
        scan_k<0><<<4, 1024>>>();
        hist2_k <<<680, 256>>>();
        scan_k<1><<<5, 1024>>>();
        update_k<<<LC_ / 256, 256>>>(zin[si], y, msk, zout[si], base_a, base_b, h_lam);
    }
}

// round 12
// speedup vs baseline: 2.0011x; 1.0027x over previous
#include <cuda_runtime.h>
#include <cuda_bf16.h>
#include <math.h>
#include <stdint.h>

#define B_  16
#define L_  1024
#define C_  128
#define H_  512
#define LC_ (L_*C_)      // 131072
#define M_  (B_*L_)      // 16384

// ---------------- device scratch ----------------
__device__ float g_eps[M_*C_];
__device__ float g_za [M_*C_];
__device__ float g_zb [M_*C_];
__device__ float g_ent[LC_];
__device__ float g_p1[(L_/2)*(C_/2)];   // 32768
__device__ float g_p2[(L_/4)*(C_/4)];   // 8192
__device__ float g_p3[(L_/8)*(C_/8)];   // 2048
__device__ float g_part[1024];          // 128 used per half
__device__ float g_T[4];
__device__ float g_stats[2];
__device__ unsigned g_hist[4 * 65536];  // zero-invariant across replays
__device__ unsigned g_pref[4];
__device__ unsigned g_krem[4];
// weight splits (3-term), transposed [N,K] row-major (K contiguous)
__device__ __nv_bfloat16 g_b1t0[H_*C_], g_b1t1[H_*C_], g_b1t2[H_*C_]; // [512,128]
__device__ __nv_bfloat16 g_b2t0[C_*H_], g_b2t1[C_*H_], g_b2t2[C_*H_]; // [128,512]

__constant__ int c_K[4] = { 26214, 6553, 1638, 409 };   // int(0.2 * pooled.size)

// ---------------- helpers ----------------
__device__ __forceinline__ uint32_t smem_u32(const void* p) {
    uint32_t a;
    asm("{ .reg .u64 t; cvta.to.shared.u64 t, %1; cvt.u32.u64 %0, t; }" : "=r"(a) : "l"(p));
    return a;
}
__device__ __forceinline__ void cp_async16(uint32_t s, const void* g) {
    asm volatile("cp.async.cg.shared.global [%0], [%1], 16;" :: "r"(s), "l"(g) : "memory");
}
#define STS32v(addr, r0) \
    asm volatile("st.shared.b32 [%0], %1;" :: "r"(addr), "r"(r0) : "memory")
#define STS64v(addr, r0, r1) \
    asm volatile("st.shared.v2.b32 [%0], {%1,%2};" :: "r"(addr), "r"(r0), "r"(r1) : "memory")
__device__ __forceinline__ void ldsm_x4(uint32_t* r, uint32_t addr) {
    asm volatile("ldmatrix.sync.aligned.m8n8.x4.shared.b16 {%0,%1,%2,%3}, [%4];"
                 : "=r"(r[0]), "=r"(r[1]), "=r"(r[2]), "=r"(r[3]) : "r"(addr));
}
__device__ __forceinline__ void mma16816(float* d, const uint32_t* a, const uint32_t* b) {
    asm volatile(
        "mma.sync.aligned.m16n8k16.row.col.f32.bf16.bf16.f32 "
        "{%0,%1,%2,%3}, {%4,%5,%6,%7}, {%8,%9}, {%0,%1,%2,%3};"
        : "+f"(d[0]), "+f"(d[1]), "+f"(d[2]), "+f"(d[3])
        : "r"(a[0]), "r"(a[1]), "r"(a[2]), "r"(a[3]), "r"(b[0]), "r"(b[1]));
}
// gelu(x) = x * sigmoid(2u); exactly 2 MUFU, no branch. (validated R10)
__device__ __forceinline__ float gelu_f(float x) {
    float x2 = x * x;
    float u  = 0.7978845608028654f * x + 0.035677408136300125f * x * x2;
    float e, r;
    asm("ex2.approx.f32 %0, %1;" : "=f"(e) : "f"(-2.8853900817779268f * u));
    asm("rcp.approx.f32 %0, %1;" : "=f"(r) : "f"(1.0f + e));
    return x * r;
}
__device__ __forceinline__ void split3(float x, unsigned short& h0, unsigned short& h1, unsigned short& h2) {
    __nv_bfloat16 b0 = __float2bfloat16_rn(x);
    float r1 = x - __bfloat162float(b0);
    __nv_bfloat16 b1 = __float2bfloat16_rn(r1);
    float r2 = r1 - __bfloat162float(b1);
    __nv_bfloat16 b2 = __float2bfloat16_rn(r2);
    h0 = __bfloat16_as_ushort(b0);
    h1 = __bfloat16_as_ushort(b1);
    h2 = __bfloat16_as_ushort(b2);
}

// ---------------- weight prep: transpose + 3-way split ------------------
__global__ __launch_bounds__(256) void prep_k(const float* __restrict__ W1, const float* __restrict__ W2)
{
    int t = blockIdx.x * 256 + threadIdx.x;   // 131072 total
    float x; int idx;
    __nv_bfloat16 *d0, *d1, *d2;
    if (t < H_ * C_) {                        // B1t [512,128] from W1[128,512]
        idx = t; int n = idx >> 7, k = idx & 127;
        x = W1[k * H_ + n];
        d0 = g_b1t0; d1 = g_b1t1; d2 = g_b1t2;
    } else {                                  // B2t [128,512] from W2[512,128]
        idx = t - H_ * C_; int n = idx >> 9, k = idx & 511;
        x = W2[k * C_ + n];
        d0 = g_b2t0; d1 = g_b2t1; d2 = g_b2t2;
    }
    unsigned short h0, h1, h2;
    split3(x, h0, h1, h2);
    d0[idx] = __ushort_as_bfloat16(h0);
    d1[idx] = __ushort_as_bfloat16(h1);
    d2[idx] = __ushort_as_bfloat16(h2);
}

static constexpr int TERMB = 10240;   // 128 rows x 80B (64B data + 16B pad)

// ================= FUSED GEMM1+GEMM2, one wave ==========================
// eps[M,128] = (gelu(z[M,128]@W1 + b1 + t*tw)) @ W2 + b2
// grid=128 m-tiles, 256 thr, 8 warps (64x32 warp tiles).
// smem: AZ (z split, 12*TERMB) | H (h split, 3*TERMB) | Bbuf (2 x 3*TERMB)
static constexpr int OFF_H  = 12 * TERMB;             // 122880
static constexpr int OFF_B  = 15 * TERMB;             // 153600
static constexpr int SMEMBF = 21 * TERMB;             // 215040

__global__ __launch_bounds__(256, 1)
void gemm12_k(const float* __restrict__ A,
              const __nv_bfloat16* __restrict__ B1t0, const __nv_bfloat16* __restrict__ B1t1,
              const __nv_bfloat16* __restrict__ B1t2,
              const __nv_bfloat16* __restrict__ B2t0, const __nv_bfloat16* __restrict__ B2t1,
              const __nv_bfloat16* __restrict__ B2t2,
              const float* __restrict__ b1, const float* __restrict__ tw, float t_feat,
              const float* __restrict__ b2, float* __restrict__ out)
{
    extern __shared__ char smem[];
    const uint32_t sb = smem_u32(smem);
    const int tid = threadIdx.x, lane = tid & 31, wid = tid >> 5;
    const int m0 = blockIdx.x * 128;
    const int wm = (wid >> 2) * 64, wn = (wid & 3) * 32;

    // B tile stream: q = 0..31 -> (n = q>>3, phase = (q>>2)&1, kt = q&3)
    auto cpB = [&](int q, int buf) {
        int n = q >> 3, ph = (q >> 2) & 1, kt = q & 3;
        const __nv_bfloat16* s0 = ph ? B2t0 : B1t0;
        const __nv_bfloat16* s1 = ph ? B2t1 : B1t1;
        const __nv_bfloat16* s2 = ph ? B2t2 : B1t2;
        uint32_t base = sb + OFF_B + buf * (3 * TERMB);
#pragma unroll
        for (int i = 0; i < 6; i++) {
            int rem = (i & 1) * 256 + tid;
            int row = rem >> 2, ch = rem & 3;
            const __nv_bfloat16* src = (i < 2) ? s0 : ((i < 4) ? s1 : s2);
            size_t off = ph ? ((size_t)row * H_ + n * 128 + kt * 32 + ch * 8)
                            : ((size_t)(n * 128 + row) * C_ + kt * 32 + ch * 8);
            cp_async16(base + (i >> 1) * TERMB + row * 80 + ch * 16, src + off);
        }
        asm volatile("cp.async.commit_group;" ::: "memory");
    };

    cpB(0, 0);

    // A prologue: split z tile into AZ (term t, kchunk c at (t*4+c)*TERMB)
#pragma unroll
    for (int c = 0; c < 4; c++) {
        float4 aR[4];
#pragma unroll
        for (int i = 0; i < 4; i++) {
            int f = tid + i * 256;
            aR[i] = *(const float4*)(A + (size_t)(m0 + (f >> 3)) * C_ + c * 32 + (f & 7) * 4);
        }
#pragma unroll
        for (int i = 0; i < 4; i++) {
            int f = tid + i * 256;
            float x[4] = { aR[i].x, aR[i].y, aR[i].z, aR[i].w };
            unsigned short s0[4], s1[4], s2[4];
#pragma unroll
            for (int j = 0; j < 4; j++) split3(x[j], s0[j], s1[j], s2[j]);
            uint32_t addr = sb + c * TERMB + (f >> 3) * 80 + (f & 7) * 8;
            STS64v(addr,             (uint32_t)s0[0] | ((uint32_t)s0[1] << 16),
                                     (uint32_t)s0[2] | ((uint32_t)s0[3] << 16));
            STS64v(addr + 4 * TERMB, (uint32_t)s1[0] | ((uint32_t)s1[1] << 16),
                                     (uint32_t)s1[2] | ((uint32_t)s1[3] << 16));
            STS64v(addr + 8 * TERMB, (uint32_t)s2[0] | ((uint32_t)s2[1] << 16),
                                     (uint32_t)s2[2] | ((uint32_t)s2[3] << 16));
        }
    }

    const int PA[6] = { 0, 0, 1, 1, 0, 2 };
    const int PB[6] = { 0, 1, 0, 1, 2, 0 };
    int buf = 0;

    float acc2[4][4][4];
#pragma unroll
    for (int a = 0; a < 4; a++)
#pragma unroll
        for (int b = 0; b < 4; b++)
#pragma unroll
            for (int c = 0; c < 4; c++) acc2[a][b][c] = 0.0f;

#pragma unroll 1
    for (int n = 0; n < 4; n++) {
        float acc1[4][4][4];
#pragma unroll
        for (int a = 0; a < 4; a++)
#pragma unroll
            for (int b = 0; b < 4; b++)
#pragma unroll
                for (int c = 0; c < 4; c++) acc1[a][b][c] = 0.0f;

        // ---- phase 0: h n-tile = z @ W1[:, n-tile] ----
#pragma unroll 1
        for (int kt = 0; kt < 4; kt++) {
            int q = n * 8 + kt;
            cpB(q + 1, buf ^ 1);
            asm volatile("cp.async.wait_group 1;" ::: "memory");
            __syncthreads();

            uint32_t baseB = sb + OFF_B + buf * (3 * TERMB);
#pragma unroll
            for (int kk = 0; kk < 2; kk++) {
                uint32_t aF[3][4][4];
                uint32_t bF[3][4][2];
#pragma unroll
                for (int t = 0; t < 3; t++) {
#pragma unroll
                    for (int mi = 0; mi < 4; mi++) {
                        uint32_t addr = sb + (t * 4 + kt) * TERMB
                            + (wm + mi * 16 + (lane & 15)) * 80
                            + kk * 32 + (lane >> 4) * 16;
                        ldsm_x4(aF[t][mi], addr);
                    }
#pragma unroll
                    for (int nt = 0; nt < 2; nt++) {
                        int row = wn + nt * 16 + ((lane >> 4) & 1) * 8 + (lane & 7);
                        uint32_t addr = baseB + t * TERMB
                            + row * 80 + kk * 32 + ((lane >> 3) & 1) * 16;
                        uint32_t r[4];
                        ldsm_x4(r, addr);
                        bF[t][nt * 2][0]     = r[0]; bF[t][nt * 2][1]     = r[1];
                        bF[t][nt * 2 + 1][0] = r[2]; bF[t][nt * 2 + 1][1] = r[3];
                    }
                }
#pragma unroll
                for (int p = 0; p < 6; p++) {
#pragma unroll
                    for (int mi = 0; mi < 4; mi++)
#pragma unroll
                        for (int ni = 0; ni < 4; ni++)
                            mma16816(acc1[mi][ni], aF[PA[p]][mi], bF[PB[p]][ni]);
                }
            }
            __syncthreads();
            buf ^= 1;
        }

        // ---- h epilogue: gelu + split3 directly into H smem ----
        // (previous n's H reads all completed; AZ reads this iter done at sync)
#pragma unroll
        for (int mi = 0; mi < 4; mi++) {
#pragma unroll
            for (int ni = 0; ni < 4; ni++) {
                int r0 = wm + mi * 16 + (lane >> 2);
                int r1 = r0 + 8;
                int cl = wn + ni * 8 + (lane & 3) * 2;       // local h col 0..127
                int cg = n * 128 + cl;                        // global h col
                float bz0 = __ldg(b1 + cg)     + t_feat * __ldg(tw + cg);
                float bz1 = __ldg(b1 + cg + 1) + t_feat * __ldg(tw + cg + 1);
                float v00 = gelu_f(acc1[mi][ni][0] + bz0);
                float v01 = gelu_f(acc1[mi][ni][1] + bz1);
                float v10 = gelu_f(acc1[mi][ni][2] + bz0);
                float v11 = gelu_f(acc1[mi][ni][3] + bz1);
                unsigned short a0, a1, a2, c0, c1, c2;
                uint32_t ad0 = sb + OFF_H + r0 * 80 + cl * 2;
                uint32_t ad1 = sb + OFF_H + r1 * 80 + cl * 2;
                split3(v00, a0, a1, a2); split3(v01, c0, c1, c2);
                STS32v(ad0,             (uint32_t)a0 | ((uint32_t)c0 << 16));
                STS32v(ad0 + TERMB,     (uint32_t)a1 | ((uint32_t)c1 << 16));
                STS32v(ad0 + 2 * TERMB, (uint32_t)a2 | ((uint32_t)c2 << 16));
                split3(v10, a0, a1, a2); split3(v11, c0, c1, c2);
                STS32v(ad1,             (uint32_t)a0 | ((uint32_t)c0 << 16));
                STS32v(ad1 + TERMB,     (uint32_t)a1 | ((uint32_t)c1 << 16));
                STS32v(ad1 + 2 * TERMB, (uint32_t)a2 | ((uint32_t)c2 << 16));
            }
        }
        __syncthreads();

        // ---- phase 1: acc2 += h n-tile @ W2[k-chunk n, :] ----
#pragma unroll 1
        for (int kt = 0; kt < 4; kt++) {
            int q = n * 8 + 4 + kt;
            if (q + 1 < 32) {
                cpB(q + 1, buf ^ 1);
                asm volatile("cp.async.wait_group 1;" ::: "memory");
            } else {
                asm volatile("cp.async.wait_group 0;" ::: "memory");
            }
            __syncthreads();

            uint32_t baseB = sb + OFF_B + buf * (3 * TERMB);
#pragma unroll
            for (int kk = 0; kk < 2; kk++) {
                uint32_t aF[3][4][4];
                uint32_t bF[3][4][2];
#pragma unroll
                for (int t = 0; t < 3; t++) {
#pragma unroll
                    for (int mi = 0; mi < 4; mi++) {
                        uint32_t addr = sb + OFF_H + t * TERMB
                            + (wm + mi * 16 + (lane & 15)) * 80
                            + kt * 32 + kk * 32 - kk * 32   // placeholder removed below
                            ;
                        // H cols for this kt: kt*32 + kk*16-part handled like std: col base = kt*32
                        addr = sb + OFF_H + t * TERMB
                            + (wm + mi * 16 + (lane & 15)) * 80
                            + kt * 32 + kk * 32;
                        // NOTE: kt*32 selects 32-col chunk; kk selects 32B half? keep std pattern:
                        addr = sb + OFF_H + t * TERMB
                            + (wm + mi * 16 + (lane & 15)) * 80
                            + (kt & 1) * 32 + (kt >> 1) * 0;  // unused
                        addr = sb + OFF_H + t * TERMB
                            + (wm + mi * 16 + (lane & 15)) * 80
                            + kt * 0;  // unused
                        // final correct: 64B of k per (kt? no) — H has 128 k-cols = 256B? no:
                        // H row = 128 bf16 = 256B?? row stride is 80B = 64B data = 32 bf16!
                        addr = 0; (void)addr;
                        uint32_t a2_ = sb + OFF_H + (t * 4 + kt) * 0; (void)a2_;
                        uint32_t fin = sb + OFF_H + t * TERMB
                            + (wm + mi * 16 + (lane & 15)) * 80
                            + kk * 32 + (lane >> 4) * 16;
                        (void)fin;
                        ldsm_x4(aF[t][mi], fin);
                    }
                }
                (void)bF;
                break;
            }
            __syncthreads();
            buf ^= 1;
        }
        break;
    }
    // SAFEGUARD: the above phase-1 sketch is wrong; real implementation below.
    (void)acc2; (void)b2; (void)out;
}

// The fused kernel above had a layout bug risk; use the verified split pair.
// (Fallback identical to R11's proven gemm1_k / gemm2_k.)

static constexpr int A1BYTES = 12 * TERMB;
static constexpr int SMEMB1  = A1BYTES + 6 * TERMB;

__global__ __launch_bounds__(256, 1)
void gemm1_k(const float* __restrict__ A,
             const __nv_bfloat16* __restrict__ Bt0, const __nv_bfloat16* __restrict__ Bt1,
             const __nv_bfloat16* __restrict__ Bt2,
             const float* __restrict__ bias, const float* __restrict__ tw, float t_feat,
             float* __restrict__ out)
{
    extern __shared__ char smem[];
    const uint32_t sb = smem_u32(smem);
    const int tid = threadIdx.x, lane = tid & 31, wid = tid >> 5;
    const int m0 = blockIdx.x * 128;
    const int wm = (wid >> 2) * 64, wn = (wid & 3) * 32;

    auto cpB = [&](int n, int kt, int buf) {
        uint32_t base = sb + A1BYTES + buf * (3 * TERMB);
#pragma unroll
        for (int i = 0; i < 6; i++) {
            int rem = (i & 1) * 256 + tid;
            int row = rem >> 2, ch = rem & 3;
            const __nv_bfloat16* src = (i < 2) ? Bt0 : ((i < 4) ? Bt1 : Bt2);
            cp_async16(base + (i >> 1) * TERMB + row * 80 + ch * 16,
                       src + (size_t)(n * 128 + row) * C_ + kt * 32 + ch * 8);
        }
        asm volatile("cp.async.commit_group;" ::: "memory");
    };

    cpB(0, 0, 0);

#pragma unroll
    for (int c = 0; c < 4; c++) {
        float4 aR[4];
#pragma unroll
        for (int i = 0; i < 4; i++) {
            int f = tid + i * 256;
            aR[i] = *(const float4*)(A + (size_t)(m0 + (f >> 3)) * C_ + c * 32 + (f & 7) * 4);
        }
#pragma unroll
        for (int i = 0; i < 4; i++) {
            int f = tid + i * 256;
            float x[4] = { aR[i].x, aR[i].y, aR[i].z, aR[i].w };
            unsigned short s0[4], s1[4], s2[4];
#pragma unroll
            for (int j = 0; j < 4; j++) split3(x[j], s0[j], s1[j], s2[j]);
            uint32_t addr = sb + c * TERMB + (f >> 3) * 80 + (f & 7) * 8;
            STS64v(addr,                 (uint32_t)s0[0] | ((uint32_t)s0[1] << 16),
                                         (uint32_t)s0[2] | ((uint32_t)s0[3] << 16));
            STS64v(addr + 4 * TERMB,     (uint32_t)s1[0] | ((uint32_t)s1[1] << 16),
                                         (uint32_t)s1[2] | ((uint32_t)s1[3] << 16));
            STS64v(addr + 8 * TERMB,     (uint32_t)s2[0] | ((uint32_t)s2[1] << 16),
                                         (uint32_t)s2[2] | ((uint32_t)s2[3] << 16));
        }
    }

    const int PA[6] = { 0, 0, 1, 1, 0, 2 };
    const int PB[6] = { 0, 1, 0, 1, 2, 0 };
    int buf = 0;

#pragma unroll 1
    for (int n = 0; n < 4; n++) {
        float acc[4][4][4];
#pragma unroll
        for (int a = 0; a < 4; a++)
#pragma unroll
            for (int b = 0; b < 4; b++)
#pragma unroll
                for (int c = 0; c < 4; c++) acc[a][b][c] = 0.0f;

#pragma unroll 1
        for (int kt = 0; kt < 4; kt++) {
            int idx = n * 4 + kt;
            if (idx + 1 < 16) {
                int nn = (idx + 1) >> 2, nk = (idx + 1) & 3;
                cpB(nn, nk, buf ^ 1);
                asm volatile("cp.async.wait_group 1;" ::: "memory");
            } else {
                asm volatile("cp.async.wait_group 0;" ::: "memory");
            }
            __syncthreads();

            uint32_t baseB = sb + A1BYTES + buf * (3 * TERMB);
#pragma unroll
            for (int kk = 0; kk < 2; kk++) {
                uint32_t aF[3][4][4];
                uint32_t bF[3][4][2];
#pragma unroll
                for (int t = 0; t < 3; t++) {
#pragma unroll
                    for (int mi = 0; mi < 4; mi++) {
                        uint32_t addr = sb + (t * 4 + kt) * TERMB
                            + (wm + mi * 16 + (lane & 15)) * 80
                            + kk * 32 + (lane >> 4) * 16;
                        ldsm_x4(aF[t][mi], addr);
                    }
#pragma unroll
                    for (int nt = 0; nt < 2; nt++) {
                        int row = wn + nt * 16 + ((lane >> 4) & 1) * 8 + (lane & 7);
                        uint32_t addr = baseB + t * TERMB
                            + row * 80 + kk * 32 + ((lane >> 3) & 1) * 16;
                        uint32_t r[4];
                        ldsm_x4(r, addr);
                        bF[t][nt * 2][0]     = r[0]; bF[t][nt * 2][1]     = r[1];
                        bF[t][nt * 2 + 1][0] = r[2]; bF[t][nt * 2 + 1][1] = r[3];
                    }
                }
#pragma unroll
                for (int p = 0; p < 6; p++) {
#pragma unroll
                    for (int mi = 0; mi < 4; mi++)
#pragma unroll
                        for (int ni = 0; ni < 4; ni++)
                            mma16816(acc[mi][ni], aF[PA[p]][mi], bF[PB[p]][ni]);
                }
            }
            __syncthreads();
            buf ^= 1;
        }

        int n0 = n * 128;
#pragma unroll
        for (int mi = 0; mi < 4; mi++) {
#pragma unroll
            for (int ni = 0; ni < 4; ni++) {
                int r0 = m0 + wm + mi * 16 + (lane >> 2);
                int r1 = r0 + 8;
                int c  = n0 + wn + ni * 8 + (lane & 3) * 2;
                float bz0 = __ldg(bias + c)     + t_feat * __ldg(tw + c);
                float bz1 = __ldg(bias + c + 1) + t_feat * __ldg(tw + c + 1);
                float v00 = gelu_f(acc[mi][ni][0] + bz0);
                float v01 = gelu_f(acc[mi][ni][1] + bz1);
                float v10 = gelu_f(acc[mi][ni][2] + bz0);
                float v11 = gelu_f(acc[mi][ni][3] + bz1);
                *(float2*)(out + (size_t)r0 * H_ + c) = make_float2(v00, v01);
                *(float2*)(out + (size_t)r1 * H_ + c) = make_float2(v10, v11);
            }
        }
    }
}

__device__ float g_h[M_*H_];   // 32 MB hidden activations (fp32)

static constexpr int ABYTES = 2 * 3 * TERMB;
static constexpr int SMEMB2 = 2 * ABYTES;

__global__ __launch_bounds__(256, 1)
void gemm2_k(const float* __restrict__ A,
             const __nv_bfloat16* __restrict__ Bt0, const __nv_bfloat16* __restrict__ Bt1,
             const __nv_bfloat16* __restrict__ Bt2,
             const float* __restrict__ bias, float* __restrict__ out)
{
    extern __shared__ char smem[];
    const uint32_t sb = smem_u32(smem);
    const int tid = threadIdx.x, lane = tid & 31, wid = tid >> 5;
    const int m0 = blockIdx.y * 128, n0 = blockIdx.x * 128;
    const int wm = (wid >> 2) * 64, wn = (wid & 3) * 32;
    const int KTOT = H_;

    float acc[4][4][4];
#pragma unroll
    for (int a = 0; a < 4; a++)
#pragma unroll
        for (int b = 0; b < 4; b++)
#pragma unroll
            for (int c = 0; c < 4; c++) acc[a][b][c] = 0.0f;

    float4 aR[4];
    auto ldgA = [&](int kt) {
#pragma unroll
        for (int i = 0; i < 4; i++) {
            int f = tid + i * 256;
            aR[i] = *(const float4*)(A + (size_t)(m0 + (f >> 3)) * KTOT + kt * 32 + (f & 7) * 4);
        }
    };
    auto stsA = [&](int buf) {
        uint32_t base = sb + buf * (3 * TERMB);
#pragma unroll
        for (int i = 0; i < 4; i++) {
            int f = tid + i * 256;
            float x[4] = { aR[i].x, aR[i].y, aR[i].z, aR[i].w };
            unsigned short s0[4], s1[4], s2[4];
#pragma unroll
            for (int j = 0; j < 4; j++) split3(x[j], s0[j], s1[j], s2[j]);
            uint32_t addr = base + (f >> 3) * 80 + (f & 7) * 8;
            STS64v(addr,             (uint32_t)s0[0] | ((uint32_t)s0[1] << 16),
                                     (uint32_t)s0[2] | ((uint32_t)s0[3] << 16));
            STS64v(addr + TERMB,     (uint32_t)s1[0] | ((uint32_t)s1[1] << 16),
                                     (uint32_t)s1[2] | ((uint32_t)s1[3] << 16));
            STS64v(addr + 2 * TERMB, (uint32_t)s2[0] | ((uint32_t)s2[1] << 16),
                                     (uint32_t)s2[2] | ((uint32_t)s2[3] << 16));
        }
    };
    auto cpB = [&](int kt, int buf) {
        uint32_t base = sb + ABYTES + buf * (3 * TERMB);
#pragma unroll
        for (int i = 0; i < 6; i++) {
            int rem = (i & 1) * 256 + tid;
            int row = rem >> 2, ch = rem & 3;
            const __nv_bfloat16* src = (i < 2) ? Bt0 : ((i < 4) ? Bt1 : Bt2);
            cp_async16(base + (i >> 1) * TERMB + row * 80 + ch * 16,
                       src + (size_t)(n0 + row) * KTOT + kt * 32 + ch * 8);
        }
        asm volatile("cp.async.commit_group;" ::: "memory");
    };

    const int NKT = KTOT / 32;
    ldgA(0);
    cpB(0, 0);
    int buf = 0;

    const int PA[6] = { 0, 0, 1, 1, 0, 2 };
    const int PB[6] = { 0, 1, 0, 1, 2, 0 };

#pragma unroll 1
    for (int kt = 0; kt < NKT; kt++) {
        stsA(buf);
        if (kt + 1 < NKT) {
            cpB(kt + 1, buf ^ 1);
            ldgA(kt + 1);
            asm volatile("cp.async.wait_group 1;" ::: "memory");
        } else {
            asm volatile("cp.async.wait_group 0;" ::: "memory");
        }
        __syncthreads();

        uint32_t baseA = sb + buf * (3 * TERMB);
        uint32_t baseB = sb + ABYTES + buf * (3 * TERMB);
#pragma unroll
        for (int kk = 0; kk < 2; kk++) {
            uint32_t aF[3][4][4];
            uint32_t bF[3][4][2];
#pragma unroll
            for (int t = 0; t < 3; t++) {
#pragma unroll
                for (int mi = 0; mi < 4; mi++) {
                    uint32_t addr = baseA + t * TERMB
                        + (wm + mi * 16 + (lane & 15)) * 80
                        + kk * 32 + (lane >> 4) * 16;
                    ldsm_x4(aF[t][mi], addr);
                }
#pragma unroll
                for (int nt = 0; nt < 2; nt++) {
                    int row = wn + nt * 16 + ((lane >> 4) & 1) * 8 + (lane & 7);
                    uint32_t addr = baseB + t * TERMB
                        + row * 80 + kk * 32 + ((lane >> 3) & 1) * 16;
                    uint32_t r[4];
                    ldsm_x4(r, addr);
                    bF[t][nt * 2][0]     = r[0]; bF[t][nt * 2][1]     = r[1];
                    bF[t][nt * 2 + 1][0] = r[2]; bF[t][nt * 2 + 1][1] = r[3];
                }
            }
#pragma unroll
            for (int p = 0; p < 6; p++) {
#pragma unroll
                for (int mi = 0; mi < 4; mi++)
#pragma unroll
                    for (int ni = 0; ni < 4; ni++)
                        mma16816(acc[mi][ni], aF[PA[p]][mi], bF[PB[p]][ni]);
            }
        }
        __syncthreads();
        buf ^= 1;
    }

#pragma unroll
    for (int mi = 0; mi < 4; mi++) {
#pragma unroll
        for (int ni = 0; ni < 4; ni++) {
            int r0 = m0 + wm + mi * 16 + (lane >> 2);
            int r1 = r0 + 8;
            int c  = n0 + wn + ni * 8 + (lane & 3) * 2;
            float bz0 = __ldg(bias + c);
            float bz1 = __ldg(bias + c + 1);
            *(float2*)(out + (size_t)r0 * C_ + c) = make_float2(acc[mi][ni][0] + bz0, acc[mi][ni][1] + bz1);
            *(float2*)(out + (size_t)r1 * C_ + c) = make_float2(acc[mi][ni][2] + bz0, acc[mi][ni][3] + bz1);
        }
    }
}

// ---------------- fused: entropy + obs_err partials + pooling + hist16 ---
__global__ __launch_bounds__(1024)
void fstats_k(const float* __restrict__ z, const float* __restrict__ y,
              const float* __restrict__ msk)
{
    int blk = blockIdx.x;
    int tid = threadIdx.x;
    __shared__ float ent_s[1024];
    __shared__ float rs[1024], rq[1024];

    int p = blk * 1024 + tid;
    float sa = 0.0f;
#pragma unroll
    for (int b = 0; b < B_; b++) sa += fabsf(g_eps[(size_t)b * LC_ + p]);
    float e = sa * (1.0f / B_);
    g_ent[p] = e;
    ent_s[tid] = e;
    atomicAdd(&g_hist[__float_as_uint(e) >> 16], 1u);

    float ps = 0.0f, pq = 0.0f;
#pragma unroll
    for (int b = 0; b < B_; b++) {
        size_t o = (size_t)b * LC_ + p;
        float t = (z[o] - y[o]) * msk[o];
        ps += t; pq += t * t;
    }
    rs[tid] = ps; rq[tid] = pq;
    __syncthreads();
    for (int st = 512; st > 0; st >>= 1) {
        if (tid < st) { rs[tid] += rs[tid + st]; rq[tid] += rq[tid + st]; }
        __syncthreads();
    }
    if (tid == 0) { g_part[blk] = rs[0]; g_part[512 + blk] = rq[0]; }

    if (tid < 256) {   // w=2: 4x64
        int pr = tid >> 6, pc = tid & 63;
        float s = 0.0f;
        for (int a = 0; a < 2; a++)
            for (int b = 0; b < 2; b++)
                s += ent_s[(pr * 2 + a) * 128 + pc * 2 + b];
        float v = s * 0.25f;
        g_p1[(blk * 4 + pr) * 64 + pc] = v;
        atomicAdd(&g_hist[65536 + (__float_as_uint(v) >> 16)], 1u);
    }
    if (tid < 64) {  // w=4: 2x32
        int pr = tid >> 5, pc = tid & 31;
        float s = 0.0f;
        for (int a = 0; a < 4; a++)
            for (int b = 0; b < 4; b++)
                s += ent_s[(pr * 4 + a) * 128 + pc * 4 + b];
        float v = s * (1.0f / 16.0f);
        g_p2[(blk * 2 + pr) * 32 + pc] = v;
        atomicAdd(&g_hist[2 * 65536 + (__float_as_uint(v) >> 16)], 1u);
    }
    if (tid < 16) {  // w=8: 1x16
        float s = 0.0f;
        for (int a = 0; a < 8; a++)
            for (int b = 0; b < 8; b++)
                s += ent_s[a * 128 + tid * 8 + b];
        float v = s * (1.0f / 64.0f);
        g_p3[blk * 16 + tid] = v;
        atomicAdd(&g_hist[3 * 65536 + (__float_as_uint(v) >> 16)], 1u);
    }
}

// ---------------- grid-parallel two-level radix select ----------------
__device__ __forceinline__ const float* sel_elem(int g, int& s, int& i) {
    if (g < 131072)      { s = 0; i = g;          return g_ent; }
    else if (g < 163840) { s = 1; i = g - 131072; return g_p1;  }
    else if (g < 172032) { s = 2; i = g - 163840; return g_p2;  }
    else                 { s = 3; i = g - 172032; return g_p3;  }
}

__global__ __launch_bounds__(256)
void hist2_k()
{
    int g = blockIdx.x * 256 + threadIdx.x;
    int s, i;
    const float* d = sel_elem(g, s, i);
    unsigned u = __float_as_uint(d[i]);
    if ((u >> 16) == g_pref[s])
        atomicAdd(&g_hist[s * 65536 + (u & 0xFFFFu)], 1u);
}

template<int LEVEL>
__global__ __launch_bounds__(1024)
void scan_k()
{
    int s = blockIdx.x;
    int t = threadIdx.x;

    if (LEVEL == 1 && s == 4) {   // variance finalize (128 block partials)
        __shared__ float rs[128], rq[128];
        if (t < 128) { rs[t] = g_part[t]; rq[t] = g_part[512 + t]; }
        __syncthreads();
        for (int st = 64; st > 0; st >>= 1) {
            if (t < st) { rs[t] += rs[t + st]; rq[t] += rq[t + st]; }
            __syncthreads();
        }
        if (t == 0) { g_stats[0] = rs[0]; g_stats[1] = rq[0]; }
        return;
    }

    unsigned* h = g_hist + s * 65536;
    unsigned K = (LEVEL == 0) ? (unsigned)c_K[s] : g_krem[s];

    unsigned p = 0;
#pragma unroll 8
    for (int j = 0; j < 64; j++) p += h[t * 64 + j];

    __shared__ unsigned ssA[1024], ssB[1024];
    ssA[t] = p;
    __syncthreads();
    unsigned* src = ssA; unsigned* dst = ssB;
#pragma unroll
    for (int off = 1; off < 1024; off <<= 1) {
        unsigned v = src[t] + ((t + off < 1024) ? src[t + off] : 0u);
        __syncthreads();
        dst[t] = v;
        __syncthreads();
        unsigned* tmp = src; src = dst; dst = tmp;
    }
    unsigned incl = src[t];
    unsigned above = incl - p;

    if (incl >= K && above < K) {
        unsigned cum = above;
        for (int j = 63; j >= 0; j--) {
            unsigned c = h[t * 64 + j];
            if (cum + c >= K) {
                unsigned bin = (unsigned)(t * 64 + j);
                if (LEVEL == 0) { g_pref[s] = bin; g_krem[s] = K - cum; }
                else            g_T[s] = __uint_as_float((g_pref[s] << 16) | bin);
                break;
            }
            cum += c;
        }
    }
    __syncthreads();
#pragma unroll 8
    for (int j = 0; j < 64; j++) h[t * 64 + j] = 0u;
}

// ---------------- final update ----------------
__global__ __launch_bounds__(256)
void update_k(const float* __restrict__ z, const float* __restrict__ y,
              const float* __restrict__ msk, float* __restrict__ out,
              float base_a, float base_b, float h_lam)
{
    int i = blockIdx.x * 256 + threadIdx.x;
    int l = i / C_, c = i % C_;

    int sfound = -1; float ent = 0.0f;
    float v0 = g_ent[i];
    if (v0 >= g_T[0]) { sfound = 0; ent = v0; }
    else {
        float v1 = g_p1[(l >> 1) * (C_ / 2) + (c >> 1)];
        if (v1 >= g_T[1]) { sfound = 1; ent = v1; }
        else {
            float v2 = g_p2[(l >> 2) * (C_ / 4) + (c >> 2)];
            if (v2 >= g_T[2]) { sfound = 2; ent = v2; }
            else {
                float v3 = g_p3[(l >> 3) * (C_ / 8) + (c >> 3)];
                if (v3 >= g_T[3]) { sfound = 3; ent = v3; }
            }
        }
    }

    if (sfound < 0) {
#pragma unroll
        for (int b = 0; b < B_; b++) {
            size_t o = (size_t)b * LC_ + i;
            out[o] = z[o];
        }
        return;
    }

    const float invN = 1.0f / (float)(B_ * LC_);
    float mean = g_stats[0] * invN;
    float var  = g_stats[1] * invN - mean * mean;
    float inv_d = 1.0f / (var + 1e-8f);

    float om1 = (ent > 0.1f ? 1.0f : 0.0f) + (ent > 0.5f ? 1.0f : 0.0f);
    float corr = 1.0f + om1 * 0.5f * h_lam
               + om1 * (om1 - 1.0f) * (1.0f / 6.0f) * h_lam * h_lam;
    float gs = 2.0f * ent / (ent + 1.0f);
    float bb = base_b * corr;

#pragma unroll
    for (int b = 0; b < B_; b++) {
        size_t o = (size_t)b * LC_ + i;
        float zv = z[o];
        float gd = -(zv - y[o]) * msk[o] * inv_d;
        out[o] = base_a * zv - bb * g_eps[o] + gs * gd;
    }
}

// ---------------- host driver ----------------
extern "C" void kernel_launch(void* const* d_in, const int* in_sizes, int n_in,
                              void* d_out, int out_size)
{
    const float* y   = (const float*)d_in[0];
    const float* msk = (const float*)d_in[1];
    const float* z0  = (const float*)d_in[2];
    const float* W1  = (const float*)d_in[3];
    const float* b1  = (const float*)d_in[4];
    const float* W2  = (const float*)d_in[5];
    const float* b2  = (const float*)d_in[6];
    const float* tw  = (const float*)d_in[7];

    static float ac[1000];
    {
        float run = 1.0f;
        for (int i = 0; i < 1000; i++) {
            float beta = 1e-4f + (0.02f - 1e-4f) * ((float)i / 999.0f);
            run *= (1.0f - beta);
            ac[i] = run;
        }
    }
    auto alpha_at = [&](int i) { return sqrtf(ac[i]); };
    auto sigma_at = [&](int i) { return sqrtf(1.0f - ac[i]); };
    auto lam_at   = [&](int i) { return logf(alpha_at(i)) - logf(sigma_at(i)); };

    float *p_h, *p_eps, *p_za, *p_zb;
    cudaGetSymbolAddress((void**)&p_h,   g_h);
    cudaGetSymbolAddress((void**)&p_eps, g_eps);
    cudaGetSymbolAddress((void**)&p_za,  g_za);
    cudaGetSymbolAddress((void**)&p_zb,  g_zb);
    __nv_bfloat16 *b1t0, *b1t1, *b1t2, *b2t0, *b2t1, *b2t2;
    cudaGetSymbolAddress((void**)&b1t0, g_b1t0);
    cudaGetSymbolAddress((void**)&b1t1, g_b1t1);
    cudaGetSymbolAddress((void**)&b1t2, g_b1t2);
    cudaGetSymbolAddress((void**)&b2t0, g_b2t0);
    cudaGetSymbolAddress((void**)&b2t1, g_b2t1);
    cudaGetSymbolAddress((void**)&b2t2, g_b2t2);

    cudaFuncSetAttribute(gemm1_k, cudaFuncAttributeMaxDynamicSharedMemorySize, SMEMB1);
    cudaFuncSetAttribute(gemm2_k, cudaFuncAttributeMaxDynamicSharedMemorySize, SMEMB2);

    const float* zin[4]  = { z0,  p_za, p_zb, p_za };
    float*       zout[4] = { p_za, p_zb, p_za, (float*)d_out };

    prep_k<<<512, 256>>>(W1, W2);

    const int step = 1000 / 4;
    dim3 grid2(C_ / 128, M_ / 128);   // (1, 128)

    for (int si = 0; si < 4; si++) {
        int k  = 999 - si * step;
        int kp = k - step; if (kp < 0) kp = 0;
        float t_feat = (float)k / 1000.0f;
        float h_lam  = lam_at(kp) - lam_at(k);
        float base_a = alpha_at(kp) / alpha_at(k);
        float base_b = sigma_at(kp) * (expf(h_lam) - 1.0f);

        gemm1_k<<<M_ / 128, 256, SMEMB1>>>(zin[si], b1t0, b1t1, b1t2, b1, tw, t_feat, p_h);
        gemm2_k<<<grid2, 256, SMEMB2>>>(p_h, b2t0, b2t1, b2t2, b2, p_eps);
        fstats_k<<<128, 1024>>>(zin[si], y, msk);
        scan_k<0><<<4, 1024>>>();
        hist2_k <<<680, 256>>>();
        scan_k<1><<<5, 1024>>>();
        update_k<<<LC_ / 256, 256>>>(zin[si], y, msk, zout[si], base_a, base_b, h_lam);
    }
}